// round 12
// baseline (speedup 1.0000x reference)
#include <cuda_runtime.h>
#include <cuda_fp16.h>
#include <math.h>
#include <stdint.h>
#include <stddef.h>

#define N1V 8192
#define N2V 8192
#define DD  1024
#define FF  800
#define FPAD 896
#define CAPB 24
#define KEEPMAX 64
#define STHR 20.0f

// ======================= scratch (device globals) =======================
__device__ __half g_m1h[(size_t)N1V * DD];
__device__ __half g_m2h[(size_t)N2V * DD];
__device__ __half g_att1h[(size_t)N2V * DD];
__device__ __half g_att2h[(size_t)N1V * DD];
__device__ __half g_w1h[FPAD * DD];
__device__ __half g_w2h[FPAD * DD];
__device__ float g_rmax[N1V], g_rsum[N1V];
__device__ float g_cmax[N2V], g_csum[N2V];
__device__ float g_rpm[(size_t)N1V * 32], g_rps[(size_t)N1V * 32];
__device__ float g_cpm[(size_t)N2V * 64], g_cps[(size_t)N2V * 64];
// candidates: rows (alpha2): 32 blocks x 24 slots; cols (alpha1): 64 x 24
__device__ int   g_c2i[(size_t)N1V * 32 * CAPB];
__device__ float g_c2x[(size_t)N1V * 32 * CAPB];
__device__ int   g_cnt2[(size_t)N1V * 32];
__device__ int   g_c1i[(size_t)N2V * 64 * CAPB];
__device__ float g_c1x[(size_t)N2V * 64 * CAPB];
__device__ int   g_cnt1[(size_t)N2V * 64];
__device__ float g_sumv1[DD], g_sumv2[DD];
__device__ float g_tpart1[FPAD * 32], g_tpart2[FPAD * 32];

// ======================= asm helpers =======================
static __device__ __forceinline__ uint32_t smem_u32(const void* p) {
    uint32_t a;
    asm("{ .reg .u64 t; cvta.to.shared.u64 t, %1; cvt.u32.u64 %0, t; }" : "=r"(a) : "l"(p));
    return a;
}
static __device__ __forceinline__ uint64_t gaddr(const void* p) {
    uint64_t a;
    asm("cvta.to.global.u64 %0, %1;" : "=l"(a) : "l"(p));
    return a;
}
static __device__ __forceinline__ void cpa16(uint32_t dst, uint64_t src) {
    asm volatile("cp.async.cg.shared.global [%0], [%1], 16;" :: "r"(dst), "l"(src));
}
static __device__ __forceinline__ void ldsm_x4(uint32_t& r0, uint32_t& r1, uint32_t& r2, uint32_t& r3, uint32_t addr) {
    asm volatile("ldmatrix.sync.aligned.m8n8.x4.shared.b16 {%0,%1,%2,%3}, [%4];"
                 : "=r"(r0), "=r"(r1), "=r"(r2), "=r"(r3) : "r"(addr));
}
static __device__ __forceinline__ void mma16816(float* d, const uint32_t* a, uint32_t b0, uint32_t b1) {
    asm volatile("mma.sync.aligned.m16n8k16.row.col.f32.f16.f16.f32 "
                 "{%0,%1,%2,%3}, {%4,%5,%6,%7}, {%8,%9}, {%0,%1,%2,%3};"
                 : "+f"(d[0]), "+f"(d[1]), "+f"(d[2]), "+f"(d[3])
                 : "r"(a[0]), "r"(a[1]), "r"(a[2]), "r"(a[3]), "r"(b0), "r"(b1));
}
static __device__ __forceinline__ void msmerge(float& m, float& s, float mo, float so) {
    float mn = fmaxf(m, mo);
    s = s * __expf(m - mn) + so * __expf(mo - mn);
    m = mn;
}

// ======================= HMMA GEMM, 128x256 block, 64x64 warp tiles =======================
// C = A.B^T, fp16 operands, k-contig, K%32==0.
// EPI 0: NO C store. Fused: row/col softmax stat partials + candidate emission
//        (entries above per-block row/col max - STHR) with fp32 acc values.
// EPI 2: tanh(acc + bias[m]) row-summed over n-tile -> tpart[m*gridDim.x + bx], m < Mvalid.
template<int EPI>
__global__ void __launch_bounds__(256, 1)
hgemm(const __half* __restrict__ Ah, const __half* __restrict__ Bh,
      int K, int NT, int Mvalid,
      const float* __restrict__ bias, float* __restrict__ tpart,
      float* __restrict__ rpm, float* __restrict__ rps,
      float* __restrict__ cpm, float* __restrict__ cps,
      int* __restrict__ c2i, float* __restrict__ c2x, int* __restrict__ cnt2,
      int* __restrict__ c1i, float* __restrict__ c1x, int* __restrict__ cnt1)
{
    extern __shared__ char smem[];
    const uint32_t sbase = smem_u32(smem);
    const int STGSZ = 30720;   // A 10240 + B 20480
    const int tid = threadIdx.x, lane = tid & 31, wid = tid >> 5;
    const int warp_m = wid & 1;
    const int warp_n = wid >> 1;
    const int m0 = blockIdx.y * 128;
    const int n0 = blockIdx.x * 256;

    const int arow = lane & 15, acol = (lane >> 4) << 3;
    const int brow = (lane & 7) + ((lane & 16) >> 1);
    const int bcol = lane & 8;

    const uint64_t gAh = gaddr(Ah);
    const uint64_t gBh = gaddr(Bh);

    float acc[4][8][4];
#pragma unroll
    for (int i = 0; i < 4; i++)
#pragma unroll
        for (int j = 0; j < 8; j++)
#pragma unroll
            for (int k = 0; k < 4; k++) acc[i][j][k] = 0.f;

    auto load_stage = [&](int kt, int bufi) {
        const int k0 = kt * 32;
        uint32_t sb = sbase + bufi * STGSZ;
#pragma unroll
        for (int i = 0; i < 2; i++) {
            int idx = tid + i * 256;
            int r = idx >> 2, c = (idx & 3) << 3;
            cpa16(sb + (uint32_t)(r * 40 + c) * 2, gAh + ((uint64_t)(m0 + r) * K + k0 + c) * 2);
        }
#pragma unroll
        for (int i = 0; i < 4; i++) {
            int idx = tid + i * 256;
            int r = idx >> 2, c = (idx & 3) << 3;
            cpa16(sb + 10240 + (uint32_t)(r * 40 + c) * 2, gBh + ((uint64_t)(n0 + r) * K + k0 + c) * 2);
        }
        asm volatile("cp.async.commit_group;" ::: "memory");
    };

    load_stage(0, 0);
    load_stage(1, 1);
    for (int t = 0; t < NT; t++) {
        if (t + 2 < NT) {
            load_stage(t + 2, (t + 2) % 3);
            asm volatile("cp.async.wait_group 2;" ::: "memory");
        } else if (t + 1 < NT) {
            asm volatile("cp.async.wait_group 1;" ::: "memory");
        } else {
            asm volatile("cp.async.wait_group 0;" ::: "memory");
        }
        __syncthreads();
        uint32_t sa = sbase + (t % 3) * STGSZ;
#pragma unroll
        for (int ks = 0; ks < 2; ks++) {
            uint32_t ah[4][4];
#pragma unroll
            for (int mf = 0; mf < 4; mf++) {
                uint32_t addr = sa + (uint32_t)((warp_m * 64 + mf * 16 + arow) * 40 + ks * 16 + acol) * 2;
                ldsm_x4(ah[mf][0], ah[mf][1], ah[mf][2], ah[mf][3], addr);
            }
            uint32_t bh[4][4];
#pragma unroll
            for (int nf2 = 0; nf2 < 4; nf2++) {
                uint32_t addr = sa + 10240 + (uint32_t)((warp_n * 64 + nf2 * 16 + brow) * 40 + ks * 16 + bcol) * 2;
                ldsm_x4(bh[nf2][0], bh[nf2][1], bh[nf2][2], bh[nf2][3], addr);
            }
#pragma unroll
            for (int mf = 0; mf < 4; mf++)
#pragma unroll
                for (int nf = 0; nf < 8; nf++) {
                    int nf2 = nf >> 1, o = (nf & 1) * 2;
                    mma16816(acc[mf][nf], ah[mf], bh[nf2][o], bh[nf2][o + 1]);
                }
        }
        __syncthreads();
    }

    const int gr = lane >> 2, q = lane & 3;
    if (EPI == 0) {
        // ---- row stat partials ----
        float rm[8], rs[8];
#pragma unroll
        for (int mf = 0; mf < 4; mf++) {
            float ma = -1e30f, mb = -1e30f;
#pragma unroll
            for (int nf = 0; nf < 8; nf++) {
                ma = fmaxf(ma, fmaxf(acc[mf][nf][0], acc[mf][nf][1]));
                mb = fmaxf(mb, fmaxf(acc[mf][nf][2], acc[mf][nf][3]));
            }
            float sa = 0.f, sb = 0.f;
#pragma unroll
            for (int nf = 0; nf < 8; nf++) {
                sa += __expf(acc[mf][nf][0] - ma) + __expf(acc[mf][nf][1] - ma);
                sb += __expf(acc[mf][nf][2] - mb) + __expf(acc[mf][nf][3] - mb);
            }
            rm[2 * mf] = ma;  rs[2 * mf] = sa;
            rm[2 * mf + 1] = mb;  rs[2 * mf + 1] = sb;
        }
#pragma unroll
        for (int o = 1; o < 4; o <<= 1)
#pragma unroll
            for (int k = 0; k < 8; k++) {
                float mo = __shfl_xor_sync(0xffffffffu, rm[k], o);
                float so = __shfl_xor_sync(0xffffffffu, rs[k], o);
                msmerge(rm[k], rs[k], mo, so);
            }
        // ---- col stat partials ----
        float cm[16], cs[16];
#pragma unroll
        for (int nf = 0; nf < 8; nf++)
#pragma unroll
            for (int b = 0; b < 2; b++) {
                int i = nf * 2 + b;
                float mv = -1e30f;
#pragma unroll
                for (int mf = 0; mf < 4; mf++)
                    mv = fmaxf(mv, fmaxf(acc[mf][nf][b], acc[mf][nf][b + 2]));
                float sv = 0.f;
#pragma unroll
                for (int mf = 0; mf < 4; mf++)
                    sv += __expf(acc[mf][nf][b] - mv) + __expf(acc[mf][nf][b + 2] - mv);
                cm[i] = mv;  cs[i] = sv;
            }
#pragma unroll
        for (int o = 4; o < 32; o <<= 1)
#pragma unroll
            for (int k = 0; k < 16; k++) {
                float mo = __shfl_xor_sync(0xffffffffu, cm[k], o);
                float so = __shfl_xor_sync(0xffffffffu, cs[k], o);
                msmerge(cm[k], cs[k], mo, so);
            }
        float* rowm  = reinterpret_cast<float*>(smem);   // [128][4]
        float* rows_ = rowm + 512;
        float* colm  = rows_ + 512;                      // [2][256]
        float* cols_ = colm + 512;
        if (q == 0) {
#pragma unroll
            for (int mf = 0; mf < 4; mf++) {
                int lr = warp_m * 64 + mf * 16 + gr;
                rowm [lr * 4 + warp_n] = rm[2 * mf];
                rows_[lr * 4 + warp_n] = rs[2 * mf];
                rowm [(lr + 8) * 4 + warp_n] = rm[2 * mf + 1];
                rows_[(lr + 8) * 4 + warp_n] = rs[2 * mf + 1];
            }
        }
        if (lane < 4) {
#pragma unroll
            for (int nf = 0; nf < 8; nf++)
#pragma unroll
                for (int b = 0; b < 2; b++) {
                    int cc = warp_n * 64 + nf * 8 + lane * 2 + b;
                    colm [warp_m * 256 + cc] = cm[nf * 2 + b];
                    cols_[warp_m * 256 + cc] = cs[nf * 2 + b];
                }
        }
        __syncthreads();
        if (tid < 128) {
            float M = rowm[tid * 4], S = rows_[tid * 4];
#pragma unroll
            for (int w = 1; w < 4; w++) msmerge(M, S, rowm[tid * 4 + w], rows_[tid * 4 + w]);
            rpm[(size_t)(m0 + tid) * 32 + blockIdx.x] = M;
            rps[(size_t)(m0 + tid) * 32 + blockIdx.x] = S;
        }
        {
            float M = colm[tid], S = cols_[tid];
            msmerge(M, S, colm[256 + tid], cols_[256 + tid]);
            cpm[(size_t)(n0 + tid) * 64 + blockIdx.y] = M;
            cps[(size_t)(n0 + tid) * 64 + blockIdx.y] = S;
        }

        // ======== candidate emission ========
        int* cntR = reinterpret_cast<int*>(smem + 8192);    // [128][16]
        int* cntC = reinterpret_cast<int*>(smem + 16384);   // [256][16]
        const int rrank = warp_n * 4 + q;
        const int crank = warp_m * 8 + gr;
        // row thresholds + counts
        float rthr[4][2];
#pragma unroll
        for (int mf = 0; mf < 4; mf++)
#pragma unroll
            for (int h = 0; h < 2; h++) {
                int lr = warp_m * 64 + mf * 16 + gr + h * 8;
                float bm = fmaxf(fmaxf(rowm[lr * 4], rowm[lr * 4 + 1]),
                                 fmaxf(rowm[lr * 4 + 2], rowm[lr * 4 + 3]));
                float thr = bm - STHR;
                rthr[mf][h] = thr;
                int c = 0;
#pragma unroll
                for (int nf = 0; nf < 8; nf++) {
                    c += (acc[mf][nf][h * 2]     > thr) ? 1 : 0;
                    c += (acc[mf][nf][h * 2 + 1] > thr) ? 1 : 0;
                }
                cntR[lr * 16 + rrank] = c;
            }
        // col thresholds + counts
        float cthr[8][2];
#pragma unroll
        for (int nf = 0; nf < 8; nf++)
#pragma unroll
            for (int b = 0; b < 2; b++) {
                int cc = warp_n * 64 + nf * 8 + q * 2 + b;
                float thr = fmaxf(colm[cc], colm[256 + cc]) - STHR;
                cthr[nf][b] = thr;
                int c = 0;
#pragma unroll
                for (int mf = 0; mf < 4; mf++) {
                    c += (acc[mf][nf][b]     > thr) ? 1 : 0;
                    c += (acc[mf][nf][b + 2] > thr) ? 1 : 0;
                }
                cntC[cc * 16 + crank] = c;
            }
        __syncthreads();
        // row emit
#pragma unroll
        for (int mf = 0; mf < 4; mf++)
#pragma unroll
            for (int h = 0; h < 2; h++) {
                int lr = warp_m * 64 + mf * 16 + gr + h * 8;
                float thr = rthr[mf][h];
                int pre = 0;
                for (int s = 0; s < rrank; s++) pre += cntR[lr * 16 + s];
                size_t base = ((size_t)(m0 + lr) * 32 + blockIdx.x) * CAPB;
#pragma unroll
                for (int nf = 0; nf < 8; nf++)
#pragma unroll
                    for (int b = 0; b < 2; b++) {
                        float v = acc[mf][nf][h * 2 + b];
                        if (v > thr) {
                            if (pre < CAPB) {
                                c2i[base + pre] = n0 + warp_n * 64 + nf * 8 + q * 2 + b;
                                c2x[base + pre] = v;
                            }
                            pre++;
                        }
                    }
                if (rrank == 15)
                    cnt2[(size_t)(m0 + lr) * 32 + blockIdx.x] = pre < CAPB ? pre : CAPB;
            }
        // col emit
#pragma unroll
        for (int nf = 0; nf < 8; nf++)
#pragma unroll
            for (int b = 0; b < 2; b++) {
                int cc = warp_n * 64 + nf * 8 + q * 2 + b;
                float thr = cthr[nf][b];
                int pre = 0;
                for (int s = 0; s < crank; s++) pre += cntC[cc * 16 + s];
                size_t base = ((size_t)(n0 + cc) * 64 + blockIdx.y) * CAPB;
#pragma unroll
                for (int mf = 0; mf < 4; mf++)
#pragma unroll
                    for (int h = 0; h < 2; h++) {
                        float v = acc[mf][nf][b + h * 2];
                        if (v > thr) {
                            if (pre < CAPB) {
                                c1i[base + pre] = m0 + warp_m * 64 + mf * 16 + gr + h * 8;
                                c1x[base + pre] = v;
                            }
                            pre++;
                        }
                    }
                if (crank == 15)
                    cnt1[(size_t)(n0 + cc) * 64 + blockIdx.y] = pre < CAPB ? pre : CAPB;
            }
    } else {
        float rsum[8];
#pragma unroll
        for (int k = 0; k < 8; k++) rsum[k] = 0.f;
#pragma unroll
        for (int mf = 0; mf < 4; mf++) {
            int row = m0 + warp_m * 64 + mf * 16 + gr;
            float bj0 = (row < Mvalid)     ? bias[row]     : 0.f;
            float bj1 = (row + 8 < Mvalid) ? bias[row + 8] : 0.f;
#pragma unroll
            for (int nf = 0; nf < 8; nf++) {
                rsum[mf * 2]     += tanhf(acc[mf][nf][0] + bj0) + tanhf(acc[mf][nf][1] + bj0);
                rsum[mf * 2 + 1] += tanhf(acc[mf][nf][2] + bj1) + tanhf(acc[mf][nf][3] + bj1);
            }
        }
#pragma unroll
        for (int o = 1; o < 4; o <<= 1)
#pragma unroll
            for (int k = 0; k < 8; k++) rsum[k] += __shfl_xor_sync(0xffffffffu, rsum[k], o);
        __syncthreads();
        float* red = reinterpret_cast<float*>(smem);
        if (q == 0) {
#pragma unroll
            for (int mf = 0; mf < 4; mf++) {
                int lr = warp_m * 64 + mf * 16 + gr;
                red[lr * 4 + warp_n]       = rsum[mf * 2];
                red[(lr + 8) * 4 + warp_n] = rsum[mf * 2 + 1];
            }
        }
        __syncthreads();
        if (tid < 128) {
            float s = red[tid * 4] + red[tid * 4 + 1] + red[tid * 4 + 2] + red[tid * 4 + 3];
            int f = m0 + tid;
            if (f < Mvalid) tpart[(size_t)f * gridDim.x + blockIdx.x] = s;
        }
    }
}

// ======================= merge softmax stat partials =======================
__global__ void stats_merge_kernel()
{
    int g = blockIdx.x * 8 + (threadIdx.x >> 5);
    int lane = threadIdx.x & 31;
    if (g < N1V) {
        float m = g_rpm[(size_t)g * 32 + lane];
        float s = g_rps[(size_t)g * 32 + lane];
#pragma unroll
        for (int o = 16; o; o >>= 1) {
            float mo = __shfl_xor_sync(0xffffffffu, m, o);
            float so = __shfl_xor_sync(0xffffffffu, s, o);
            msmerge(m, s, mo, so);
        }
        if (lane == 0) { g_rmax[g] = m; g_rsum[g] = s; }
    } else {
        int c = g - N1V;
        float m = g_cpm[(size_t)c * 64 + lane];
        float s = g_cps[(size_t)c * 64 + lane];
        msmerge(m, s, g_cpm[(size_t)c * 64 + 32 + lane], g_cps[(size_t)c * 64 + 32 + lane]);
#pragma unroll
        for (int o = 16; o; o >>= 1) {
            float mo = __shfl_xor_sync(0xffffffffu, m, o);
            float so = __shfl_xor_sync(0xffffffffu, s, o);
            msmerge(m, s, mo, so);
        }
        if (lane == 0) { g_cmax[c] = m; g_csum[c] = s; }
    }
}

// ======================= refine + gather (fused) =======================
// Per output row: filter candidates by global threshold, exact fp32 logits,
// exact (M, S) reconstruction, exact weights, weighted gather -> att fp16.
__global__ void refine_gather_kernel(const float* __restrict__ Avec, const float* __restrict__ Bmat,
                                     const int* __restrict__ cnt, const int* __restrict__ ci,
                                     const float* __restrict__ cx, int NB,
                                     const float* __restrict__ gM, const float* __restrict__ gS,
                                     __half* __restrict__ att)
{
    __shared__ float a[DD];
    __shared__ int   jl[KEEPMAX];
    __shared__ float xap[KEEPMAX], xl[KEEPMAX], wl[KEEPMAX];
    __shared__ float red[8];
    __shared__ int nk;
    int row = blockIdx.x;
    int t = threadIdx.x, lane = t & 31, w = t >> 5;
    float gmax = gM[row];
    float thr = gmax - STHR;

    if (t == 0) {
        int k = 0;
        for (int bx = 0; bx < NB; bx++) {
            int c = cnt[(size_t)row * NB + bx];
            size_t base = ((size_t)row * NB + bx) * CAPB;
            for (int s = 0; s < c; s++) {
                float x = cx[base + s];
                if (x > thr && k < KEEPMAX) {
                    jl[k] = ci[base + s];
                    xap[k] = x;
                    k++;
                }
            }
        }
        nk = k;
    }
#pragma unroll
    for (int k = 0; k < 4; k++) a[t + k * 256] = Avec[(size_t)row * DD + t + k * 256];
    __syncthreads();

    int n = nk;
    for (int s = 0; s < n; s++) {
        const float* b = Bmat + (size_t)jl[s] * DD;
        float p = 0.f;
#pragma unroll
        for (int k = 0; k < 4; k++) p += a[t + k * 256] * b[t + k * 256];
#pragma unroll
        for (int o = 16; o; o >>= 1) p += __shfl_xor_sync(0xffffffffu, p, o);
        if (lane == 0) red[w] = p;
        __syncthreads();
        if (t == 0) xl[s] = red[0] + red[1] + red[2] + red[3] + red[4] + red[5] + red[6] + red[7];
        __syncthreads();
    }
    if (t == 0) {
        float Mn = gmax;
        for (int s = 0; s < n; s++) Mn = fmaxf(Mn, xl[s]);
        float S = gS[row] * __expf(gmax - Mn);
        for (int s = 0; s < n; s++)
            S += __expf(xl[s] - Mn) - __expf(xap[s] - Mn);
        float inv = 1.0f / S;
        for (int s = 0; s < n; s++) wl[s] = __expf(xl[s] - Mn) * inv;
    }
    __syncthreads();

    float a0 = 0.f, a1 = 0.f, a2 = 0.f, a3 = 0.f;
    for (int s = 0; s < n; s++) {
        float wv = wl[s];
        float4 v = *reinterpret_cast<const float4*>(Bmat + (size_t)jl[s] * DD + t * 4);
        a0 += wv * v.x; a1 += wv * v.y; a2 += wv * v.z; a3 += wv * v.w;
    }
    __half2* d = reinterpret_cast<__half2*>(att + (size_t)row * DD + t * 4);
    d[0] = __floats2half2_rn(a0, a1);
    d[1] = __floats2half2_rn(a2, a3);
}

// ======================= column sums of fp16 att -> sumv =======================
__global__ void colsum_kernel(const __half* __restrict__ att, float* __restrict__ sumv)
{
    int lane = threadIdx.x & 31, w = threadIdx.x >> 5;
    int col = blockIdx.x * 32 + lane;
    float s = 0.f;
#pragma unroll 8
    for (int r = 0; r < 1024; r++)
        s += __half2float(att[(size_t)(w * 1024 + r) * DD + col]);
    __shared__ float sh[8][33];
    sh[w][lane] = s;
    __syncthreads();
    if (threadIdx.x < 32) {
        float t = 0.f;
#pragma unroll
        for (int q = 0; q < 8; q++) t += sh[q][threadIdx.x];
        sumv[blockIdx.x * 32 + threadIdx.x] = t;
    }
}

// ======================= prep: fp32 -> fp16 cast (row-padded) =======================
__global__ void cast_kernel(const float* __restrict__ src, __half* __restrict__ dh,
                            int R, int C, int Rpad)
{
    int idx = blockIdx.x * 256 + threadIdx.x;
    if (idx >= Rpad * C) return;
    int r = idx / C;
    float v = (r < R) ? src[idx] : 0.f;
    dh[idx] = __float2half_rn(v);
}

// ======================= finalize =======================
__global__ void finalize_kernel(const float* __restrict__ Wf1, const float* __restrict__ bf1,
                                const float* __restrict__ Wf2, const float* __restrict__ bf2,
                                float* __restrict__ out)
{
    int g = blockIdx.x * 8 + (threadIdx.x >> 5);
    int lane = threadIdx.x & 31;
    const float inv = 1.0f / 8192.0f;
    if (g < FF) {
        const float* w = Wf1 + (size_t)g * DD;
        float d = 0.f;
        for (int l = lane; l < DD; l += 32) d += w[l] * g_sumv2[l];
#pragma unroll
        for (int o = 16; o; o >>= 1) d += __shfl_xor_sync(0xffffffffu, d, o);
        if (lane == 0) {
            float filt = 1.0f / (1.0f + __expf(-(d * inv + bf1[g])));
            float t = 0.f;
#pragma unroll
            for (int b = 0; b < 32; b++) t += g_tpart1[g * 32 + b];
            out[g] = t * inv * filt;
        }
    } else if (g < 2 * FF) {
        int f = g - FF;
        const float* w = Wf2 + (size_t)f * DD;
        float d = 0.f;
        for (int l = lane; l < DD; l += 32) d += w[l] * g_sumv1[l];
#pragma unroll
        for (int o = 16; o; o >>= 1) d += __shfl_xor_sync(0xffffffffu, d, o);
        if (lane == 0) {
            float filt = 1.0f / (1.0f + __expf(-(d * inv + bf2[f])));
            float t = 0.f;
#pragma unroll
            for (int b = 0; b < 32; b++) t += g_tpart2[f * 32 + b];
            out[FF + f] = t * inv * filt;
        }
    }
}

// ======================= launch =======================
extern "C" void kernel_launch(void* const* d_in, const int* in_sizes, int n_in,
                              void* d_out, int out_size)
{
    const float* m1  = (const float*)d_in[0];
    const float* m2  = (const float*)d_in[1];
    const float* Wf1 = (const float*)d_in[2];
    const float* bf1 = (const float*)d_in[3];
    const float* Wf2 = (const float*)d_in[4];
    const float* bf2 = (const float*)d_in[5];
    const float* W1  = (const float*)d_in[6];
    const float* b1  = (const float*)d_in[7];
    const float* W2  = (const float*)d_in[8];
    const float* b2  = (const float*)d_in[9];
    float* out = (float*)d_out;

    float *tpart1, *tpart2, *rpm, *rps, *cpm, *cps, *sumv1, *sumv2;
    float *c2x, *c1x, *rmax, *rsum, *cmax, *csum;
    int *c2i, *cnt2, *c1i, *cnt1;
    __half *m1h, *m2h, *att1h, *att2h, *w1h, *w2h;
    cudaGetSymbolAddress((void**)&m1h,   g_m1h);
    cudaGetSymbolAddress((void**)&m2h,   g_m2h);
    cudaGetSymbolAddress((void**)&att1h, g_att1h);
    cudaGetSymbolAddress((void**)&att2h, g_att2h);
    cudaGetSymbolAddress((void**)&w1h,   g_w1h);
    cudaGetSymbolAddress((void**)&w2h,   g_w2h);
    cudaGetSymbolAddress((void**)&tpart1, g_tpart1);
    cudaGetSymbolAddress((void**)&tpart2, g_tpart2);
    cudaGetSymbolAddress((void**)&rpm, g_rpm);
    cudaGetSymbolAddress((void**)&rps, g_rps);
    cudaGetSymbolAddress((void**)&cpm, g_cpm);
    cudaGetSymbolAddress((void**)&cps, g_cps);
    cudaGetSymbolAddress((void**)&c2i, g_c2i);
    cudaGetSymbolAddress((void**)&c2x, g_c2x);
    cudaGetSymbolAddress((void**)&cnt2, g_cnt2);
    cudaGetSymbolAddress((void**)&c1i, g_c1i);
    cudaGetSymbolAddress((void**)&c1x, g_c1x);
    cudaGetSymbolAddress((void**)&cnt1, g_cnt1);
    cudaGetSymbolAddress((void**)&sumv1, g_sumv1);
    cudaGetSymbolAddress((void**)&sumv2, g_sumv2);
    cudaGetSymbolAddress((void**)&rmax, g_rmax);
    cudaGetSymbolAddress((void**)&rsum, g_rsum);
    cudaGetSymbolAddress((void**)&cmax, g_cmax);
    cudaGetSymbolAddress((void**)&csum, g_csum);

    cudaFuncSetAttribute(hgemm<0>, cudaFuncAttributeMaxDynamicSharedMemorySize, 92160);
    cudaFuncSetAttribute(hgemm<2>, cudaFuncAttributeMaxDynamicSharedMemorySize, 92160);

    // 0) prep: cast inputs to fp16
    cast_kernel<<<(N1V * DD + 255) / 256, 256>>>(m1, m1h, N1V, DD, N1V);
    cast_kernel<<<(N2V * DD + 255) / 256, 256>>>(m2, m2h, N2V, DD, N2V);
    cast_kernel<<<(FPAD * DD + 255) / 256, 256>>>(W1, w1h, FF, DD, FPAD);
    cast_kernel<<<(FPAD * DD + 255) / 256, 256>>>(W2, w2h, FF, DD, FPAD);

    // 1) approx logits: fused stats + candidate emission, NO materialization
    hgemm<0><<<dim3(N2V / 256, N1V / 128), 256, 92160>>>(
        m1h, m2h, DD, DD / 32, N1V,
        nullptr, nullptr, rpm, rps, cpm, cps,
        c2i, c2x, cnt2, c1i, c1x, cnt1);

    // 2) merge approx stats (M, S)
    stats_merge_kernel<<<(N1V + N2V) / 8, 256>>>();

    // 3) refine + gather (exact logits, exact softmax, fp32 gather -> fp16 att)
    refine_gather_kernel<<<N1V, 256>>>(m1, m2, cnt2, c2i, c2x, 32, rmax, rsum, att2h);
    refine_gather_kernel<<<N2V, 256>>>(m2, m1, cnt1, c1i, c1x, 64, cmax, csum, att1h);

    // 4) column sums for the filter path
    colsum_kernel<<<DD / 32, 256>>>(att1h, sumv1);
    colsum_kernel<<<DD / 32, 256>>>(att2h, sumv2);

    // 5) transform: [F x N] = W @ att^T, fp16, fused tanh+rowsum
    hgemm<2><<<dim3(N2V / 256, FPAD / 128), 256, 92160>>>(
        w1h, att1h, DD, DD / 32, FF,
        b1, tpart1, nullptr, nullptr, nullptr, nullptr,
        nullptr, nullptr, nullptr, nullptr, nullptr, nullptr);
    hgemm<2><<<dim3(N1V / 256, FPAD / 128), 256, 92160>>>(
        w2h, att2h, DD, DD / 32, FF,
        b2, tpart2, nullptr, nullptr, nullptr, nullptr,
        nullptr, nullptr, nullptr, nullptr, nullptr, nullptr);

    // 6) filters + outputs
    finalize_kernel<<<200, 256>>>(Wf1, bf1, Wf2, bf2, out);
}

// round 13
// speedup vs baseline: 1.3130x; 1.3130x over previous
#include <cuda_runtime.h>
#include <cuda_fp16.h>
#include <math.h>
#include <stdint.h>
#include <stddef.h>

#define N1V 8192
#define N2V 8192
#define DD  1024
#define FF  800
#define FPAD 896
#define SCAP 512
#define STHR 20.0f

// ======================= scratch (device globals) =======================
__device__ float  g_raw [(size_t)N1V * N2V];    // approx logits fp32 (1-term fp16 GEMM)
__device__ __half g_m1h[(size_t)N1V * DD];
__device__ __half g_m2h[(size_t)N2V * DD];
__device__ __half g_att1h[(size_t)N2V * DD];
__device__ __half g_att2h[(size_t)N1V * DD];
__device__ __half g_w1h[FPAD * DD];
__device__ __half g_w2h[FPAD * DD];
__device__ float g_rmax[N1V], g_rsum[N1V];
__device__ float g_cmax[N2V], g_csum[N2V];
__device__ float g_rpm[(size_t)N1V * 32], g_rps[(size_t)N1V * 32];   // row stat partials
__device__ float g_cpm[(size_t)N2V * 64], g_cps[(size_t)N2V * 64];   // col stat partials
__device__ int   g_sel2_idx[(size_t)N1V * SCAP];   // row-softmax (alpha2) selections
__device__ float g_sel2_w  [(size_t)N1V * SCAP];
__device__ int   g_sel2_cnt[N1V];
__device__ int   g_sel1_idx[(size_t)N2V * SCAP];   // col-softmax (alpha1) selections
__device__ float g_sel1_w  [(size_t)N2V * SCAP];
__device__ int   g_sel1_cnt[N2V];
__device__ float g_sumv1[DD], g_sumv2[DD];
__device__ float g_tpart1[FPAD * 32], g_tpart2[FPAD * 32];

// ======================= asm helpers =======================
static __device__ __forceinline__ uint32_t smem_u32(const void* p) {
    uint32_t a;
    asm("{ .reg .u64 t; cvta.to.shared.u64 t, %1; cvt.u32.u64 %0, t; }" : "=r"(a) : "l"(p));
    return a;
}
static __device__ __forceinline__ uint64_t gaddr(const void* p) {
    uint64_t a;
    asm("cvta.to.global.u64 %0, %1;" : "=l"(a) : "l"(p));
    return a;
}
static __device__ __forceinline__ void cpa16(uint32_t dst, uint64_t src) {
    asm volatile("cp.async.cg.shared.global [%0], [%1], 16;" :: "r"(dst), "l"(src));
}
static __device__ __forceinline__ void ldsm_x4(uint32_t& r0, uint32_t& r1, uint32_t& r2, uint32_t& r3, uint32_t addr) {
    asm volatile("ldmatrix.sync.aligned.m8n8.x4.shared.b16 {%0,%1,%2,%3}, [%4];"
                 : "=r"(r0), "=r"(r1), "=r"(r2), "=r"(r3) : "r"(addr));
}
static __device__ __forceinline__ void mma16816(float* d, const uint32_t* a, uint32_t b0, uint32_t b1) {
    asm volatile("mma.sync.aligned.m16n8k16.row.col.f32.f16.f16.f32 "
                 "{%0,%1,%2,%3}, {%4,%5,%6,%7}, {%8,%9}, {%0,%1,%2,%3};"
                 : "+f"(d[0]), "+f"(d[1]), "+f"(d[2]), "+f"(d[3])
                 : "r"(a[0]), "r"(a[1]), "r"(a[2]), "r"(a[3]), "r"(b0), "r"(b1));
}
static __device__ __forceinline__ void msmerge(float& m, float& s, float mo, float so) {
    float mn = fmaxf(m, mo);
    s = s * __expf(m - mn) + so * __expf(mo - mn);
    m = mn;
}
// fast tanh via exp2-based __expf; clamped (tanh(15) == 1 in fp32)
static __device__ __forceinline__ float fast_tanh(float x) {
    x = fminf(fmaxf(x, -15.f), 15.f);
    float e = __expf(2.f * x);
    return (e - 1.f) / (e + 1.f);
}

// ======================= HMMA GEMM, 128x256 block, 64x64 warp tiles =======================
// C[M,N] = sum_k A[m,k]*B[n,k]; fp16 operands, k-contig, K%32==0.
// EPI 0: store C fp32 (pitch ldw) + row/col softmax stat partials.
// EPI 2: fast_tanh(acc + bias[m]) row-summed over n-tile -> tpart[m*gridDim.x + bx], m < Mvalid.
template<int EPI>
__global__ void __launch_bounds__(256, 1)
hgemm(const __half* __restrict__ Ah, const __half* __restrict__ Bh,
      float* __restrict__ C, long ldw, int K, int NT, int Mvalid,
      const float* __restrict__ bias, float* __restrict__ tpart,
      float* __restrict__ rpm, float* __restrict__ rps,
      float* __restrict__ cpm, float* __restrict__ cps)
{
    extern __shared__ char smem[];
    const uint32_t sbase = smem_u32(smem);
    const int STGSZ = 30720;   // A 10240 + B 20480
    const int tid = threadIdx.x, lane = tid & 31, wid = tid >> 5;
    const int warp_m = wid & 1;
    const int warp_n = wid >> 1;
    const int m0 = blockIdx.y * 128;
    const int n0 = blockIdx.x * 256;

    const int arow = lane & 15, acol = (lane >> 4) << 3;
    const int brow = (lane & 7) + ((lane & 16) >> 1);
    const int bcol = lane & 8;

    const uint64_t gAh = gaddr(Ah);
    const uint64_t gBh = gaddr(Bh);

    float acc[4][8][4];
#pragma unroll
    for (int i = 0; i < 4; i++)
#pragma unroll
        for (int j = 0; j < 8; j++)
#pragma unroll
            for (int k = 0; k < 4; k++) acc[i][j][k] = 0.f;

    auto load_stage = [&](int kt, int bufi) {
        const int k0 = kt * 32;
        uint32_t sb = sbase + bufi * STGSZ;
#pragma unroll
        for (int i = 0; i < 2; i++) {
            int idx = tid + i * 256;
            int r = idx >> 2, c = (idx & 3) << 3;
            cpa16(sb + (uint32_t)(r * 40 + c) * 2, gAh + ((uint64_t)(m0 + r) * K + k0 + c) * 2);
        }
#pragma unroll
        for (int i = 0; i < 4; i++) {
            int idx = tid + i * 256;
            int r = idx >> 2, c = (idx & 3) << 3;
            cpa16(sb + 10240 + (uint32_t)(r * 40 + c) * 2, gBh + ((uint64_t)(n0 + r) * K + k0 + c) * 2);
        }
        asm volatile("cp.async.commit_group;" ::: "memory");
    };

    load_stage(0, 0);
    load_stage(1, 1);
    for (int t = 0; t < NT; t++) {
        if (t + 2 < NT) {
            load_stage(t + 2, (t + 2) % 3);
            asm volatile("cp.async.wait_group 2;" ::: "memory");
        } else if (t + 1 < NT) {
            asm volatile("cp.async.wait_group 1;" ::: "memory");
        } else {
            asm volatile("cp.async.wait_group 0;" ::: "memory");
        }
        __syncthreads();
        uint32_t sa = sbase + (t % 3) * STGSZ;
#pragma unroll
        for (int ks = 0; ks < 2; ks++) {
            uint32_t ah[4][4];
#pragma unroll
            for (int mf = 0; mf < 4; mf++) {
                uint32_t addr = sa + (uint32_t)((warp_m * 64 + mf * 16 + arow) * 40 + ks * 16 + acol) * 2;
                ldsm_x4(ah[mf][0], ah[mf][1], ah[mf][2], ah[mf][3], addr);
            }
            uint32_t bh[4][4];
#pragma unroll
            for (int nf2 = 0; nf2 < 4; nf2++) {
                uint32_t addr = sa + 10240 + (uint32_t)((warp_n * 64 + nf2 * 16 + brow) * 40 + ks * 16 + bcol) * 2;
                ldsm_x4(bh[nf2][0], bh[nf2][1], bh[nf2][2], bh[nf2][3], addr);
            }
#pragma unroll
            for (int mf = 0; mf < 4; mf++)
#pragma unroll
                for (int nf = 0; nf < 8; nf++) {
                    int nf2 = nf >> 1, o = (nf & 1) * 2;
                    mma16816(acc[mf][nf], ah[mf], bh[nf2][o], bh[nf2][o + 1]);
                }
        }
        __syncthreads();
    }

    const int gr = lane >> 2, q = lane & 3;
    if (EPI == 0) {
#pragma unroll
        for (int mf = 0; mf < 4; mf++)
#pragma unroll
            for (int nf = 0; nf < 8; nf++) {
                int row = m0 + warp_m * 64 + mf * 16 + gr;
                int col = n0 + warp_n * 64 + nf * 8 + q * 2;
                *reinterpret_cast<float2*>(C + (size_t)row * ldw + col) =
                    make_float2(acc[mf][nf][0], acc[mf][nf][1]);
                *reinterpret_cast<float2*>(C + (size_t)(row + 8) * ldw + col) =
                    make_float2(acc[mf][nf][2], acc[mf][nf][3]);
            }
        float rm[8], rs[8];
#pragma unroll
        for (int mf = 0; mf < 4; mf++) {
            float ma = -1e30f, mb = -1e30f;
#pragma unroll
            for (int nf = 0; nf < 8; nf++) {
                ma = fmaxf(ma, fmaxf(acc[mf][nf][0], acc[mf][nf][1]));
                mb = fmaxf(mb, fmaxf(acc[mf][nf][2], acc[mf][nf][3]));
            }
            float sa = 0.f, sb = 0.f;
#pragma unroll
            for (int nf = 0; nf < 8; nf++) {
                sa += __expf(acc[mf][nf][0] - ma) + __expf(acc[mf][nf][1] - ma);
                sb += __expf(acc[mf][nf][2] - mb) + __expf(acc[mf][nf][3] - mb);
            }
            rm[2 * mf] = ma;  rs[2 * mf] = sa;
            rm[2 * mf + 1] = mb;  rs[2 * mf + 1] = sb;
        }
#pragma unroll
        for (int o = 1; o < 4; o <<= 1)
#pragma unroll
            for (int k = 0; k < 8; k++) {
                float mo = __shfl_xor_sync(0xffffffffu, rm[k], o);
                float so = __shfl_xor_sync(0xffffffffu, rs[k], o);
                msmerge(rm[k], rs[k], mo, so);
            }
        float cm[16], cs[16];
#pragma unroll
        for (int nf = 0; nf < 8; nf++)
#pragma unroll
            for (int b = 0; b < 2; b++) {
                int i = nf * 2 + b;
                float mv = -1e30f;
#pragma unroll
                for (int mf = 0; mf < 4; mf++)
                    mv = fmaxf(mv, fmaxf(acc[mf][nf][b], acc[mf][nf][b + 2]));
                float sv = 0.f;
#pragma unroll
                for (int mf = 0; mf < 4; mf++)
                    sv += __expf(acc[mf][nf][b] - mv) + __expf(acc[mf][nf][b + 2] - mv);
                cm[i] = mv;  cs[i] = sv;
            }
#pragma unroll
        for (int o = 4; o < 32; o <<= 1)
#pragma unroll
            for (int k = 0; k < 16; k++) {
                float mo = __shfl_xor_sync(0xffffffffu, cm[k], o);
                float so = __shfl_xor_sync(0xffffffffu, cs[k], o);
                msmerge(cm[k], cs[k], mo, so);
            }
        float* rowm  = reinterpret_cast<float*>(smem);
        float* rows_ = rowm + 512;
        float* colm  = rows_ + 512;
        float* cols_ = colm + 512;
        if (q == 0) {
#pragma unroll
            for (int mf = 0; mf < 4; mf++) {
                int lr = warp_m * 64 + mf * 16 + gr;
                rowm [lr * 4 + warp_n] = rm[2 * mf];
                rows_[lr * 4 + warp_n] = rs[2 * mf];
                rowm [(lr + 8) * 4 + warp_n] = rm[2 * mf + 1];
                rows_[(lr + 8) * 4 + warp_n] = rs[2 * mf + 1];
            }
        }
        if (lane < 4) {
#pragma unroll
            for (int nf = 0; nf < 8; nf++)
#pragma unroll
                for (int b = 0; b < 2; b++) {
                    int cc = warp_n * 64 + nf * 8 + lane * 2 + b;
                    colm [warp_m * 256 + cc] = cm[nf * 2 + b];
                    cols_[warp_m * 256 + cc] = cs[nf * 2 + b];
                }
        }
        __syncthreads();
        if (tid < 128) {
            float M = rowm[tid * 4], S = rows_[tid * 4];
#pragma unroll
            for (int w = 1; w < 4; w++) msmerge(M, S, rowm[tid * 4 + w], rows_[tid * 4 + w]);
            rpm[(size_t)(m0 + tid) * 32 + blockIdx.x] = M;
            rps[(size_t)(m0 + tid) * 32 + blockIdx.x] = S;
        }
        {
            float M = colm[tid], S = cols_[tid];
            msmerge(M, S, colm[256 + tid], cols_[256 + tid]);
            cpm[(size_t)(n0 + tid) * 64 + blockIdx.y] = M;
            cps[(size_t)(n0 + tid) * 64 + blockIdx.y] = S;
        }
    } else {
        float rsum[8];
#pragma unroll
        for (int k = 0; k < 8; k++) rsum[k] = 0.f;
#pragma unroll
        for (int mf = 0; mf < 4; mf++) {
            int row = m0 + warp_m * 64 + mf * 16 + gr;
            float bj0 = (row < Mvalid)     ? bias[row]     : 0.f;
            float bj1 = (row + 8 < Mvalid) ? bias[row + 8] : 0.f;
#pragma unroll
            for (int nf = 0; nf < 8; nf++) {
                rsum[mf * 2]     += fast_tanh(acc[mf][nf][0] + bj0) + fast_tanh(acc[mf][nf][1] + bj0);
                rsum[mf * 2 + 1] += fast_tanh(acc[mf][nf][2] + bj1) + fast_tanh(acc[mf][nf][3] + bj1);
            }
        }
#pragma unroll
        for (int o = 1; o < 4; o <<= 1)
#pragma unroll
            for (int k = 0; k < 8; k++) rsum[k] += __shfl_xor_sync(0xffffffffu, rsum[k], o);
        __syncthreads();
        float* red = reinterpret_cast<float*>(smem);
        if (q == 0) {
#pragma unroll
            for (int mf = 0; mf < 4; mf++) {
                int lr = warp_m * 64 + mf * 16 + gr;
                red[lr * 4 + warp_n]       = rsum[mf * 2];
                red[(lr + 8) * 4 + warp_n] = rsum[mf * 2 + 1];
            }
        }
        __syncthreads();
        if (tid < 128) {
            float s = red[tid * 4] + red[tid * 4 + 1] + red[tid * 4 + 2] + red[tid * 4 + 3];
            int f = m0 + tid;
            if (f < Mvalid) tpart[(size_t)f * gridDim.x + blockIdx.x] = s;
        }
    }
}

// ======================= merge softmax stat partials (store M and S) =======================
__global__ void stats_merge_kernel()
{
    int g = blockIdx.x * 8 + (threadIdx.x >> 5);
    int lane = threadIdx.x & 31;
    if (g < N1V) {
        float m = g_rpm[(size_t)g * 32 + lane];
        float s = g_rps[(size_t)g * 32 + lane];
#pragma unroll
        for (int o = 16; o; o >>= 1) {
            float mo = __shfl_xor_sync(0xffffffffu, m, o);
            float so = __shfl_xor_sync(0xffffffffu, s, o);
            msmerge(m, s, mo, so);
        }
        if (lane == 0) { g_rmax[g] = m; g_rsum[g] = s; }
    } else {
        int c = g - N1V;
        float m = g_cpm[(size_t)c * 64 + lane];
        float s = g_cps[(size_t)c * 64 + lane];
        msmerge(m, s, g_cpm[(size_t)c * 64 + 32 + lane], g_cps[(size_t)c * 64 + 32 + lane]);
#pragma unroll
        for (int o = 16; o; o >>= 1) {
            float mo = __shfl_xor_sync(0xffffffffu, m, o);
            float so = __shfl_xor_sync(0xffffffffu, s, o);
            msmerge(m, s, mo, so);
        }
        if (lane == 0) { g_cmax[c] = m; g_csum[c] = s; }
    }
}

// ======================= selection: rows (alpha2), single pass, indices only =======================
__global__ void select_rows_kernel()
{
    int row = blockIdx.x;
    int t = threadIdx.x, lane = t & 31, w = t >> 5;
    const float* r = g_raw + (size_t)row * N2V;
    float thr = g_rmax[row] - STHR;
    int base = t * 32;
    uint32_t mask = 0;
    int c = 0;
#pragma unroll 8
    for (int k = 0; k < 32; k++) {
        bool p = r[base + k] > thr;
        mask |= (uint32_t)p << k;
        c += p ? 1 : 0;
    }
    int v = c;
#pragma unroll
    for (int o = 1; o < 32; o <<= 1) {
        int u = __shfl_up_sync(0xffffffffu, v, o);
        if (lane >= o) v += u;
    }
    __shared__ int wt[8];
    if (lane == 31) wt[w] = v;
    __syncthreads();
    int woff = 0;
#pragma unroll
    for (int s = 0; s < 8; s++) if (s < w) woff += wt[s];
    int off = woff + v - c;
    while (mask) {
        int k = __ffs(mask) - 1;
        mask &= mask - 1;
        if (off < SCAP) g_sel2_idx[(size_t)row * SCAP + off] = base + k;
        off++;
    }
    if (t == 0) {
        int total = wt[0] + wt[1] + wt[2] + wt[3] + wt[4] + wt[5] + wt[6] + wt[7];
        g_sel2_cnt[row] = total < SCAP ? total : SCAP;
    }
}

// ======================= selection: cols (alpha1), single pass via smem bitmasks =======================
__global__ void select_cols_kernel()
{
    __shared__ uint32_t masks[256][32];
    __shared__ int scnt[8][32];
    int lane = threadIdx.x & 31, w = threadIdx.x >> 5;
    int col = blockIdx.x * 32 + lane;
    float thr = g_cmax[col] - STHR;
    int r0 = w * 1024;
    int c = 0;
    for (int word = 0; word < 32; word++) {
        uint32_t m = 0;
#pragma unroll 8
        for (int b = 0; b < 32; b++) {
            bool p = g_raw[(size_t)(r0 + word * 32 + b) * N2V + col] > thr;
            m |= (uint32_t)p << b;
            c += p ? 1 : 0;
        }
        masks[threadIdx.x][word] = m;
    }
    scnt[w][lane] = c;
    __syncthreads();
    int off = 0, total = 0;
#pragma unroll
    for (int s = 0; s < 8; s++) {
        if (s < w) off += scnt[s][lane];
        total += scnt[s][lane];
    }
    for (int word = 0; word < 32; word++) {
        uint32_t m = masks[threadIdx.x][word];
        while (m) {
            int b = __ffs(m) - 1;
            m &= m - 1;
            if (off < SCAP) g_sel1_idx[(size_t)col * SCAP + off] = r0 + word * 32 + b;
            off++;
        }
    }
    if (w == 0) g_sel1_cnt[col] = total < SCAP ? total : SCAP;
}

// ======================= refine: exact fp32 logits + exact stats for selected entries =======================
__global__ void refine_kernel(const float* __restrict__ Arow, const float* __restrict__ Bmat,
                              const int* __restrict__ cnt, const int* __restrict__ idx,
                              float* __restrict__ wgt,
                              const float* __restrict__ gM, const float* __restrict__ gS,
                              const float* __restrict__ rawp, long rawPitch, int rawIsRow)
{
    __shared__ float a[DD];
    __shared__ float xs[SCAP];
    __shared__ float red[8];
    int row = blockIdx.x;
    int t = threadIdx.x, lane = t & 31, w = t >> 5;
    int n = cnt[row];
#pragma unroll
    for (int k = 0; k < 4; k++) a[t + k * 256] = Arow[(size_t)row * DD + t + k * 256];
    __syncthreads();
    for (int s = 0; s < n; s++) {
        int j = idx[(size_t)row * SCAP + s];
        const float* b = Bmat + (size_t)j * DD;
        float p = 0.f;
#pragma unroll
        for (int k = 0; k < 4; k++) p += a[t + k * 256] * b[t + k * 256];
#pragma unroll
        for (int o = 16; o; o >>= 1) p += __shfl_xor_sync(0xffffffffu, p, o);
        if (lane == 0) red[w] = p;
        __syncthreads();
        if (t == 0) xs[s] = red[0] + red[1] + red[2] + red[3] + red[4] + red[5] + red[6] + red[7];
        __syncthreads();
    }
    if (t == 0) {
        float Mapp = gM[row], Sapp = gS[row];
        float Mn = -1e30f;
        for (int s = 0; s < n; s++) Mn = fmaxf(Mn, xs[s]);
        float S = Sapp * __expf(Mapp - Mn);
        for (int s = 0; s < n; s++) {
            int j = idx[(size_t)row * SCAP + s];
            float xa = rawIsRow ? rawp[(size_t)row * rawPitch + j]
                                : rawp[(size_t)j * rawPitch + row];
            S += __expf(xs[s] - Mn) - __expf(xa - Mn);
        }
        float inv = 1.0f / S;
        for (int s = 0; s < n; s++)
            wgt[(size_t)row * SCAP + s] = __expf(xs[s] - Mn) * inv;
    }
}

// ======================= gather: att[row] = sum_t w_t * src[idx_t] =======================
__global__ void gather_att_kernel(const int* __restrict__ cnt, const int* __restrict__ idx,
                                  const float* __restrict__ wgt, const float* __restrict__ src,
                                  __half* __restrict__ dst)
{
    int row = blockIdx.x;
    int t = threadIdx.x;
    int n = cnt[row];
    float a0 = 0.f, a1 = 0.f, a2 = 0.f, a3 = 0.f;
    for (int k = 0; k < n; k++) {
        int j = idx[(size_t)row * SCAP + k];
        float w = wgt[(size_t)row * SCAP + k];
        float4 v = *reinterpret_cast<const float4*>(src + (size_t)j * DD + t * 4);
        a0 += w * v.x; a1 += w * v.y; a2 += w * v.z; a3 += w * v.w;
    }
    __half2* d = reinterpret_cast<__half2*>(dst + (size_t)row * DD + t * 4);
    d[0] = __floats2half2_rn(a0, a1);
    d[1] = __floats2half2_rn(a2, a3);
}

// ======================= column sums of fp16 att -> sumv =======================
__global__ void colsum_kernel(const __half* __restrict__ att, float* __restrict__ sumv)
{
    int lane = threadIdx.x & 31, w = threadIdx.x >> 5;
    int col = blockIdx.x * 32 + lane;
    float s = 0.f;
#pragma unroll 8
    for (int r = 0; r < 1024; r++)
        s += __half2float(att[(size_t)(w * 1024 + r) * DD + col]);
    __shared__ float sh[8][33];
    sh[w][lane] = s;
    __syncthreads();
    if (threadIdx.x < 32) {
        float t = 0.f;
#pragma unroll
        for (int q = 0; q < 8; q++) t += sh[q][threadIdx.x];
        sumv[blockIdx.x * 32 + threadIdx.x] = t;
    }
}

// ======================= prep: fp32 -> fp16 cast (row-padded) =======================
__global__ void cast_kernel(const float* __restrict__ src, __half* __restrict__ dh,
                            int R, int C, int Rpad)
{
    int idx = blockIdx.x * 256 + threadIdx.x;
    if (idx >= Rpad * C) return;
    int r = idx / C;
    float v = (r < R) ? src[idx] : 0.f;
    dh[idx] = __float2half_rn(v);
}

// ======================= finalize =======================
__global__ void finalize_kernel(const float* __restrict__ Wf1, const float* __restrict__ bf1,
                                const float* __restrict__ Wf2, const float* __restrict__ bf2,
                                float* __restrict__ out)
{
    int g = blockIdx.x * 8 + (threadIdx.x >> 5);
    int lane = threadIdx.x & 31;
    const float inv = 1.0f / 8192.0f;
    if (g < FF) {
        const float* w = Wf1 + (size_t)g * DD;
        float d = 0.f;
        for (int l = lane; l < DD; l += 32) d += w[l] * g_sumv2[l];
#pragma unroll
        for (int o = 16; o; o >>= 1) d += __shfl_xor_sync(0xffffffffu, d, o);
        if (lane == 0) {
            float filt = 1.0f / (1.0f + __expf(-(d * inv + bf1[g])));
            float t = 0.f;
#pragma unroll
            for (int b = 0; b < 32; b++) t += g_tpart1[g * 32 + b];
            out[g] = t * inv * filt;
        }
    } else if (g < 2 * FF) {
        int f = g - FF;
        const float* w = Wf2 + (size_t)f * DD;
        float d = 0.f;
        for (int l = lane; l < DD; l += 32) d += w[l] * g_sumv1[l];
#pragma unroll
        for (int o = 16; o; o >>= 1) d += __shfl_xor_sync(0xffffffffu, d, o);
        if (lane == 0) {
            float filt = 1.0f / (1.0f + __expf(-(d * inv + bf2[f])));
            float t = 0.f;
#pragma unroll
            for (int b = 0; b < 32; b++) t += g_tpart2[f * 32 + b];
            out[FF + f] = t * inv * filt;
        }
    }
}

// ======================= launch =======================
extern "C" void kernel_launch(void* const* d_in, const int* in_sizes, int n_in,
                              void* d_out, int out_size)
{
    const float* m1  = (const float*)d_in[0];
    const float* m2  = (const float*)d_in[1];
    const float* Wf1 = (const float*)d_in[2];
    const float* bf1 = (const float*)d_in[3];
    const float* Wf2 = (const float*)d_in[4];
    const float* bf2 = (const float*)d_in[5];
    const float* W1  = (const float*)d_in[6];
    const float* b1  = (const float*)d_in[7];
    const float* W2  = (const float*)d_in[8];
    const float* b2  = (const float*)d_in[9];
    float* out = (float*)d_out;

    float *raw, *tpart1, *tpart2, *rpm, *rps, *cpm, *cps, *sumv1, *sumv2;
    float *sel2w, *sel1w, *rmax, *rsum, *cmax, *csum;
    int *sel2i, *sel2c, *sel1i, *sel1c;
    __half *m1h, *m2h, *att1h, *att2h, *w1h, *w2h;
    cudaGetSymbolAddress((void**)&raw,   g_raw);
    cudaGetSymbolAddress((void**)&m1h,   g_m1h);
    cudaGetSymbolAddress((void**)&m2h,   g_m2h);
    cudaGetSymbolAddress((void**)&att1h, g_att1h);
    cudaGetSymbolAddress((void**)&att2h, g_att2h);
    cudaGetSymbolAddress((void**)&w1h,   g_w1h);
    cudaGetSymbolAddress((void**)&w2h,   g_w2h);
    cudaGetSymbolAddress((void**)&tpart1, g_tpart1);
    cudaGetSymbolAddress((void**)&tpart2, g_tpart2);
    cudaGetSymbolAddress((void**)&rpm, g_rpm);
    cudaGetSymbolAddress((void**)&rps, g_rps);
    cudaGetSymbolAddress((void**)&cpm, g_cpm);
    cudaGetSymbolAddress((void**)&cps, g_cps);
    cudaGetSymbolAddress((void**)&sel2i, g_sel2_idx);
    cudaGetSymbolAddress((void**)&sel2w, g_sel2_w);
    cudaGetSymbolAddress((void**)&sel2c, g_sel2_cnt);
    cudaGetSymbolAddress((void**)&sel1i, g_sel1_idx);
    cudaGetSymbolAddress((void**)&sel1w, g_sel1_w);
    cudaGetSymbolAddress((void**)&sel1c, g_sel1_cnt);
    cudaGetSymbolAddress((void**)&sumv1, g_sumv1);
    cudaGetSymbolAddress((void**)&sumv2, g_sumv2);
    cudaGetSymbolAddress((void**)&rmax, g_rmax);
    cudaGetSymbolAddress((void**)&rsum, g_rsum);
    cudaGetSymbolAddress((void**)&cmax, g_cmax);
    cudaGetSymbolAddress((void**)&csum, g_csum);

    cudaFuncSetAttribute(hgemm<0>, cudaFuncAttributeMaxDynamicSharedMemorySize, 92160);
    cudaFuncSetAttribute(hgemm<2>, cudaFuncAttributeMaxDynamicSharedMemorySize, 92160);

    // 0) prep: cast inputs to fp16
    cast_kernel<<<(N1V * DD + 255) / 256, 256>>>(m1, m1h, N1V, DD, N1V);
    cast_kernel<<<(N2V * DD + 255) / 256, 256>>>(m2, m2h, N2V, DD, N2V);
    cast_kernel<<<(FPAD * DD + 255) / 256, 256>>>(W1, w1h, FF, DD, FPAD);
    cast_kernel<<<(FPAD * DD + 255) / 256, 256>>>(W2, w2h, FF, DD, FPAD);

    // 1) approx raw = m1 @ m2^T, K=1024, pure fp16 1-term + fused softmax stat partials
    hgemm<0><<<dim3(N2V / 256, N1V / 128), 256, 92160>>>(
        m1h, m2h, raw, N2V, DD, DD / 32, N1V,
        nullptr, nullptr, rpm, rps, cpm, cps);

    // 2) merge approx stats (M, S)
    stats_merge_kernel<<<(N1V + N2V) / 8, 256>>>();

    // 3) threshold selection (20-nat margin; approx errors ~7e-3 are irrelevant)
    select_rows_kernel<<<N1V, 256>>>();
    select_cols_kernel<<<N2V / 32, 256>>>();

    // 4) refine: exact fp32 logits for selected entries, exact (M, S), exact weights
    refine_kernel<<<N1V, 256>>>(m1, m2, sel2c, sel2i, sel2w, rmax, rsum, raw, N2V, 1);
    refine_kernel<<<N2V, 256>>>(m2, m1, sel1c, sel1i, sel1w, cmax, csum, raw, N2V, 0);

    // 5) gather attended matrices in fp32, store fp16
    gather_att_kernel<<<N1V, 256>>>(sel2c, sel2i, sel2w, m2, att2h);
    gather_att_kernel<<<N2V, 256>>>(sel1c, sel1i, sel1w, m1, att1h);

    // 6) column sums for the filter path
    colsum_kernel<<<DD / 32, 256>>>(att1h, sumv1);
    colsum_kernel<<<DD / 32, 256>>>(att2h, sumv2);

    // 7) transform: [F x N] = W @ att^T, fp16, fused fast_tanh+rowsum
    hgemm<2><<<dim3(N2V / 256, FPAD / 128), 256, 92160>>>(
        w1h, att1h, nullptr, 0, DD, DD / 32, FF,
        b1, tpart1, nullptr, nullptr, nullptr, nullptr);
    hgemm<2><<<dim3(N1V / 256, FPAD / 128), 256, 92160>>>(
        w2h, att2h, nullptr, 0, DD, DD / 32, FF,
        b2, tpart2, nullptr, nullptr, nullptr, nullptr);

    // 8) filters + outputs
    finalize_kernel<<<200, 256>>>(Wf1, bf1, Wf2, bf2, out);
}

// round 14
// speedup vs baseline: 1.4572x; 1.1099x over previous
#include <cuda_runtime.h>
#include <cuda_fp16.h>
#include <math.h>
#include <stdint.h>
#include <stddef.h>

#define N1V 8192
#define N2V 8192
#define DD  1024
#define FF  800
#define FPAD 896
#define SCAP 512
#define STHR 20.0f

// ======================= scratch (device globals) =======================
__device__ __half g_rawh[(size_t)N1V * N2V];    // approx logits fp16
__device__ __half g_m1h[(size_t)N1V * DD];
__device__ __half g_m2h[(size_t)N2V * DD];
__device__ __half g_att1h[(size_t)N2V * DD];
__device__ __half g_att2h[(size_t)N1V * DD];
__device__ __half g_w1h[FPAD * DD];
__device__ __half g_w2h[FPAD * DD];
__device__ float g_rmax[N1V], g_rsum[N1V];
__device__ float g_cmax[N2V], g_csum[N2V];
__device__ float g_rpm[(size_t)N1V * 32], g_rps[(size_t)N1V * 32];   // row stat partials
__device__ float g_cpm[(size_t)N2V * 64], g_cps[(size_t)N2V * 64];   // col stat partials
__device__ int   g_sel2_idx[(size_t)N1V * SCAP];
__device__ int   g_sel2_cnt[N1V];
__device__ int   g_sel1_idx[(size_t)N2V * SCAP];
__device__ int   g_sel1_cnt[N2V];
__device__ float g_sumv1[DD], g_sumv2[DD];
__device__ float g_tpart1[FPAD * 32], g_tpart2[FPAD * 32];

// ======================= asm helpers =======================
static __device__ __forceinline__ uint32_t smem_u32(const void* p) {
    uint32_t a;
    asm("{ .reg .u64 t; cvta.to.shared.u64 t, %1; cvt.u32.u64 %0, t; }" : "=r"(a) : "l"(p));
    return a;
}
static __device__ __forceinline__ uint64_t gaddr(const void* p) {
    uint64_t a;
    asm("cvta.to.global.u64 %0, %1;" : "=l"(a) : "l"(p));
    return a;
}
static __device__ __forceinline__ void cpa16(uint32_t dst, uint64_t src) {
    asm volatile("cp.async.cg.shared.global [%0], [%1], 16;" :: "r"(dst), "l"(src));
}
static __device__ __forceinline__ void ldsm_x4(uint32_t& r0, uint32_t& r1, uint32_t& r2, uint32_t& r3, uint32_t addr) {
    asm volatile("ldmatrix.sync.aligned.m8n8.x4.shared.b16 {%0,%1,%2,%3}, [%4];"
                 : "=r"(r0), "=r"(r1), "=r"(r2), "=r"(r3) : "r"(addr));
}
static __device__ __forceinline__ void mma16816(float* d, const uint32_t* a, uint32_t b0, uint32_t b1) {
    asm volatile("mma.sync.aligned.m16n8k16.row.col.f32.f16.f16.f32 "
                 "{%0,%1,%2,%3}, {%4,%5,%6,%7}, {%8,%9}, {%0,%1,%2,%3};"
                 : "+f"(d[0]), "+f"(d[1]), "+f"(d[2]), "+f"(d[3])
                 : "r"(a[0]), "r"(a[1]), "r"(a[2]), "r"(a[3]), "r"(b0), "r"(b1));
}
static __device__ __forceinline__ void msmerge(float& m, float& s, float mo, float so) {
    float mn = fmaxf(m, mo);
    s = s * __expf(m - mn) + so * __expf(mo - mn);
    m = mn;
}

// ======================= HMMA GEMM, 128x256 block, 64x64 warp tiles =======================
// C[M,N] = sum_k A[m,k]*B[n,k]; fp16 operands, k-contig, K%32==0.
// EPI 0: round acc to fp16, store Ch, compute row/col softmax stat partials from ROUNDED values.
// EPI 2: tanhf(acc + bias[m]) row-summed over n-tile -> tpart[m*gridDim.x + bx], m < Mvalid.
//        blockIdx.z selects operand set (A/B/bias/tpart vs A2/B2/bias2/tpart2).
template<int EPI>
__global__ void __launch_bounds__(256, 1)
hgemm(const __half* __restrict__ Ah, const __half* __restrict__ Bh,
      const __half* __restrict__ Ah2, const __half* __restrict__ Bh2,
      __half* __restrict__ Ch, long ldw, int K, int NT, int Mvalid,
      const float* __restrict__ bias, float* __restrict__ tpart,
      const float* __restrict__ bias2, float* __restrict__ tpart2,
      float* __restrict__ rpm, float* __restrict__ rps,
      float* __restrict__ cpm, float* __restrict__ cps)
{
    extern __shared__ char smem[];
    const uint32_t sbase = smem_u32(smem);
    const int STGSZ = 30720;   // A 10240 + B 20480
    const int tid = threadIdx.x, lane = tid & 31, wid = tid >> 5;
    const int warp_m = wid & 1;
    const int warp_n = wid >> 1;
    const int m0 = blockIdx.y * 128;
    const int n0 = blockIdx.x * 256;

    const __half* Aop = (EPI == 2 && blockIdx.z) ? Ah2 : Ah;
    const __half* Bop = (EPI == 2 && blockIdx.z) ? Bh2 : Bh;

    const int arow = lane & 15, acol = (lane >> 4) << 3;
    const int brow = (lane & 7) + ((lane & 16) >> 1);
    const int bcol = lane & 8;

    const uint64_t gAh = gaddr(Aop);
    const uint64_t gBh = gaddr(Bop);

    float acc[4][8][4];
#pragma unroll
    for (int i = 0; i < 4; i++)
#pragma unroll
        for (int j = 0; j < 8; j++)
#pragma unroll
            for (int k = 0; k < 4; k++) acc[i][j][k] = 0.f;

    auto load_stage = [&](int kt, int bufi) {
        const int k0 = kt * 32;
        uint32_t sb = sbase + bufi * STGSZ;
#pragma unroll
        for (int i = 0; i < 2; i++) {
            int idx = tid + i * 256;
            int r = idx >> 2, c = (idx & 3) << 3;
            cpa16(sb + (uint32_t)(r * 40 + c) * 2, gAh + ((uint64_t)(m0 + r) * K + k0 + c) * 2);
        }
#pragma unroll
        for (int i = 0; i < 4; i++) {
            int idx = tid + i * 256;
            int r = idx >> 2, c = (idx & 3) << 3;
            cpa16(sb + 10240 + (uint32_t)(r * 40 + c) * 2, gBh + ((uint64_t)(n0 + r) * K + k0 + c) * 2);
        }
        asm volatile("cp.async.commit_group;" ::: "memory");
    };

    load_stage(0, 0);
    load_stage(1, 1);
    for (int t = 0; t < NT; t++) {
        if (t + 2 < NT) {
            load_stage(t + 2, (t + 2) % 3);
            asm volatile("cp.async.wait_group 2;" ::: "memory");
        } else if (t + 1 < NT) {
            asm volatile("cp.async.wait_group 1;" ::: "memory");
        } else {
            asm volatile("cp.async.wait_group 0;" ::: "memory");
        }
        __syncthreads();
        uint32_t sa = sbase + (t % 3) * STGSZ;
#pragma unroll
        for (int ks = 0; ks < 2; ks++) {
            uint32_t ah[4][4];
#pragma unroll
            for (int mf = 0; mf < 4; mf++) {
                uint32_t addr = sa + (uint32_t)((warp_m * 64 + mf * 16 + arow) * 40 + ks * 16 + acol) * 2;
                ldsm_x4(ah[mf][0], ah[mf][1], ah[mf][2], ah[mf][3], addr);
            }
            uint32_t bh[4][4];
#pragma unroll
            for (int nf2 = 0; nf2 < 4; nf2++) {
                uint32_t addr = sa + 10240 + (uint32_t)((warp_n * 64 + nf2 * 16 + brow) * 40 + ks * 16 + bcol) * 2;
                ldsm_x4(bh[nf2][0], bh[nf2][1], bh[nf2][2], bh[nf2][3], addr);
            }
#pragma unroll
            for (int mf = 0; mf < 4; mf++)
#pragma unroll
                for (int nf = 0; nf < 8; nf++) {
                    int nf2 = nf >> 1, o = (nf & 1) * 2;
                    mma16816(acc[mf][nf], ah[mf], bh[nf2][o], bh[nf2][o + 1]);
                }
        }
        __syncthreads();
    }

    const int gr = lane >> 2, q = lane & 3;
    if (EPI == 0) {
        // ---- round to fp16, store, replace acc with rounded values (stats consistency) ----
#pragma unroll
        for (int mf = 0; mf < 4; mf++)
#pragma unroll
            for (int nf = 0; nf < 8; nf++) {
                int row = m0 + warp_m * 64 + mf * 16 + gr;
                int col = n0 + warp_n * 64 + nf * 8 + q * 2;
                __half2 h01 = __floats2half2_rn(acc[mf][nf][0], acc[mf][nf][1]);
                __half2 h23 = __floats2half2_rn(acc[mf][nf][2], acc[mf][nf][3]);
                *reinterpret_cast<__half2*>(Ch + (size_t)row * ldw + col)       = h01;
                *reinterpret_cast<__half2*>(Ch + (size_t)(row + 8) * ldw + col) = h23;
                float2 f01 = __half22float2(h01);
                float2 f23 = __half22float2(h23);
                acc[mf][nf][0] = f01.x; acc[mf][nf][1] = f01.y;
                acc[mf][nf][2] = f23.x; acc[mf][nf][3] = f23.y;
            }
        float rm[8], rs[8];
#pragma unroll
        for (int mf = 0; mf < 4; mf++) {
            float ma = -1e30f, mb = -1e30f;
#pragma unroll
            for (int nf = 0; nf < 8; nf++) {
                ma = fmaxf(ma, fmaxf(acc[mf][nf][0], acc[mf][nf][1]));
                mb = fmaxf(mb, fmaxf(acc[mf][nf][2], acc[mf][nf][3]));
            }
            float sa = 0.f, sb = 0.f;
#pragma unroll
            for (int nf = 0; nf < 8; nf++) {
                sa += __expf(acc[mf][nf][0] - ma) + __expf(acc[mf][nf][1] - ma);
                sb += __expf(acc[mf][nf][2] - mb) + __expf(acc[mf][nf][3] - mb);
            }
            rm[2 * mf] = ma;  rs[2 * mf] = sa;
            rm[2 * mf + 1] = mb;  rs[2 * mf + 1] = sb;
        }
#pragma unroll
        for (int o = 1; o < 4; o <<= 1)
#pragma unroll
            for (int k = 0; k < 8; k++) {
                float mo = __shfl_xor_sync(0xffffffffu, rm[k], o);
                float so = __shfl_xor_sync(0xffffffffu, rs[k], o);
                msmerge(rm[k], rs[k], mo, so);
            }
        float cm[16], cs[16];
#pragma unroll
        for (int nf = 0; nf < 8; nf++)
#pragma unroll
            for (int b = 0; b < 2; b++) {
                int i = nf * 2 + b;
                float mv = -1e30f;
#pragma unroll
                for (int mf = 0; mf < 4; mf++)
                    mv = fmaxf(mv, fmaxf(acc[mf][nf][b], acc[mf][nf][b + 2]));
                float sv = 0.f;
#pragma unroll
                for (int mf = 0; mf < 4; mf++)
                    sv += __expf(acc[mf][nf][b] - mv) + __expf(acc[mf][nf][b + 2] - mv);
                cm[i] = mv;  cs[i] = sv;
            }
#pragma unroll
        for (int o = 4; o < 32; o <<= 1)
#pragma unroll
            for (int k = 0; k < 16; k++) {
                float mo = __shfl_xor_sync(0xffffffffu, cm[k], o);
                float so = __shfl_xor_sync(0xffffffffu, cs[k], o);
                msmerge(cm[k], cs[k], mo, so);
            }
        float* rowm  = reinterpret_cast<float*>(smem);
        float* rows_ = rowm + 512;
        float* colm  = rows_ + 512;
        float* cols_ = colm + 512;
        if (q == 0) {
#pragma unroll
            for (int mf = 0; mf < 4; mf++) {
                int lr = warp_m * 64 + mf * 16 + gr;
                rowm [lr * 4 + warp_n] = rm[2 * mf];
                rows_[lr * 4 + warp_n] = rs[2 * mf];
                rowm [(lr + 8) * 4 + warp_n] = rm[2 * mf + 1];
                rows_[(lr + 8) * 4 + warp_n] = rs[2 * mf + 1];
            }
        }
        if (lane < 4) {
#pragma unroll
            for (int nf = 0; nf < 8; nf++)
#pragma unroll
                for (int b = 0; b < 2; b++) {
                    int cc = warp_n * 64 + nf * 8 + lane * 2 + b;
                    colm [warp_m * 256 + cc] = cm[nf * 2 + b];
                    cols_[warp_m * 256 + cc] = cs[nf * 2 + b];
                }
        }
        __syncthreads();
        if (tid < 128) {
            float M = rowm[tid * 4], S = rows_[tid * 4];
#pragma unroll
            for (int w = 1; w < 4; w++) msmerge(M, S, rowm[tid * 4 + w], rows_[tid * 4 + w]);
            rpm[(size_t)(m0 + tid) * 32 + blockIdx.x] = M;
            rps[(size_t)(m0 + tid) * 32 + blockIdx.x] = S;
        }
        {
            float M = colm[tid], S = cols_[tid];
            msmerge(M, S, colm[256 + tid], cols_[256 + tid]);
            cpm[(size_t)(n0 + tid) * 64 + blockIdx.y] = M;
            cps[(size_t)(n0 + tid) * 64 + blockIdx.y] = S;
        }
    } else {
        const float* bs = blockIdx.z ? bias2 : bias;
        float* tp = blockIdx.z ? tpart2 : tpart;
        float rsum[8];
#pragma unroll
        for (int k = 0; k < 8; k++) rsum[k] = 0.f;
#pragma unroll
        for (int mf = 0; mf < 4; mf++) {
            int row = m0 + warp_m * 64 + mf * 16 + gr;
            float bj0 = (row < Mvalid)     ? bs[row]     : 0.f;
            float bj1 = (row + 8 < Mvalid) ? bs[row + 8] : 0.f;
#pragma unroll
            for (int nf = 0; nf < 8; nf++) {
                rsum[mf * 2]     += tanhf(acc[mf][nf][0] + bj0) + tanhf(acc[mf][nf][1] + bj0);
                rsum[mf * 2 + 1] += tanhf(acc[mf][nf][2] + bj1) + tanhf(acc[mf][nf][3] + bj1);
            }
        }
#pragma unroll
        for (int o = 1; o < 4; o <<= 1)
#pragma unroll
            for (int k = 0; k < 8; k++) rsum[k] += __shfl_xor_sync(0xffffffffu, rsum[k], o);
        __syncthreads();
        float* red = reinterpret_cast<float*>(smem);
        if (q == 0) {
#pragma unroll
            for (int mf = 0; mf < 4; mf++) {
                int lr = warp_m * 64 + mf * 16 + gr;
                red[lr * 4 + warp_n]       = rsum[mf * 2];
                red[(lr + 8) * 4 + warp_n] = rsum[mf * 2 + 1];
            }
        }
        __syncthreads();
        if (tid < 128) {
            float s = red[tid * 4] + red[tid * 4 + 1] + red[tid * 4 + 2] + red[tid * 4 + 3];
            int f = m0 + tid;
            if (f < Mvalid) tp[(size_t)f * gridDim.x + blockIdx.x] = s;
        }
    }
}

// ======================= merge softmax stat partials =======================
__global__ void stats_merge_kernel()
{
    int g = blockIdx.x * 8 + (threadIdx.x >> 5);
    int lane = threadIdx.x & 31;
    if (g < N1V) {
        float m = g_rpm[(size_t)g * 32 + lane];
        float s = g_rps[(size_t)g * 32 + lane];
#pragma unroll
        for (int o = 16; o; o >>= 1) {
            float mo = __shfl_xor_sync(0xffffffffu, m, o);
            float so = __shfl_xor_sync(0xffffffffu, s, o);
            msmerge(m, s, mo, so);
        }
        if (lane == 0) { g_rmax[g] = m; g_rsum[g] = s; }
    } else {
        int c = g - N1V;
        float m = g_cpm[(size_t)c * 64 + lane];
        float s = g_cps[(size_t)c * 64 + lane];
        msmerge(m, s, g_cpm[(size_t)c * 64 + 32 + lane], g_cps[(size_t)c * 64 + 32 + lane]);
#pragma unroll
        for (int o = 16; o; o >>= 1) {
            float mo = __shfl_xor_sync(0xffffffffu, m, o);
            float so = __shfl_xor_sync(0xffffffffu, s, o);
            msmerge(m, s, mo, so);
        }
        if (lane == 0) { g_cmax[c] = m; g_csum[c] = s; }
    }
}

// ======================= selection: rows (alpha2), single pass =======================
__global__ void select_rows_kernel()
{
    int row = blockIdx.x;
    int t = threadIdx.x, lane = t & 31, w = t >> 5;
    const __half* r = g_rawh + (size_t)row * N2V;
    float thr = g_rmax[row] - STHR;
    int base = t * 32;
    uint32_t mask = 0;
    int c = 0;
#pragma unroll 8
    for (int k = 0; k < 32; k++) {
        bool p = __half2float(r[base + k]) > thr;
        mask |= (uint32_t)p << k;
        c += p ? 1 : 0;
    }
    int v = c;
#pragma unroll
    for (int o = 1; o < 32; o <<= 1) {
        int u = __shfl_up_sync(0xffffffffu, v, o);
        if (lane >= o) v += u;
    }
    __shared__ int wt[8];
    if (lane == 31) wt[w] = v;
    __syncthreads();
    int woff = 0;
#pragma unroll
    for (int s = 0; s < 8; s++) if (s < w) woff += wt[s];
    int off = woff + v - c;
    while (mask) {
        int k = __ffs(mask) - 1;
        mask &= mask - 1;
        if (off < SCAP) g_sel2_idx[(size_t)row * SCAP + off] = base + k;
        off++;
    }
    if (t == 0) {
        int total = wt[0] + wt[1] + wt[2] + wt[3] + wt[4] + wt[5] + wt[6] + wt[7];
        g_sel2_cnt[row] = total < SCAP ? total : SCAP;
    }
}

// ======================= selection: cols (alpha1), single pass via smem bitmasks =======================
__global__ void select_cols_kernel()
{
    __shared__ uint32_t masks[256][32];
    __shared__ int scnt[8][32];
    int lane = threadIdx.x & 31, w = threadIdx.x >> 5;
    int col = blockIdx.x * 32 + lane;
    float thr = g_cmax[col] - STHR;
    int r0 = w * 1024;
    int c = 0;
    for (int word = 0; word < 32; word++) {
        uint32_t m = 0;
#pragma unroll 8
        for (int b = 0; b < 32; b++) {
            bool p = __half2float(g_rawh[(size_t)(r0 + word * 32 + b) * N2V + col]) > thr;
            m |= (uint32_t)p << b;
            c += p ? 1 : 0;
        }
        masks[threadIdx.x][word] = m;
    }
    scnt[w][lane] = c;
    __syncthreads();
    int off = 0, total = 0;
#pragma unroll
    for (int s = 0; s < 8; s++) {
        if (s < w) off += scnt[s][lane];
        total += scnt[s][lane];
    }
    for (int word = 0; word < 32; word++) {
        uint32_t m = masks[threadIdx.x][word];
        while (m) {
            int b = __ffs(m) - 1;
            m &= m - 1;
            if (off < SCAP) g_sel1_idx[(size_t)col * SCAP + off] = r0 + word * 32 + b;
            off++;
        }
    }
    if (w == 0) g_sel1_cnt[col] = total < SCAP ? total : SCAP;
}

// ======================= refine + gather (fused) =======================
// Per output row: exact fp32 logits for selected entries, exact (M, S) rebuild
// (consistent with fp16 raw via stored approx values), exact weights,
// weighted fp32 gather -> fp16 att.
__global__ void refine_gather_kernel(const float* __restrict__ Arow, const float* __restrict__ Bmat,
                                     const int* __restrict__ cnt, const int* __restrict__ idx,
                                     const float* __restrict__ gM, const float* __restrict__ gS,
                                     const __half* __restrict__ rawp, long rawPitch, int rawIsRow,
                                     __half* __restrict__ att)
{
    __shared__ float a[DD];
    __shared__ float xs[SCAP];
    __shared__ float wl[SCAP];
    __shared__ float red[8];
    int row = blockIdx.x;
    int t = threadIdx.x, lane = t & 31, w = t >> 5;
    int n = cnt[row];
#pragma unroll
    for (int k = 0; k < 4; k++) a[t + k * 256] = Arow[(size_t)row * DD + t + k * 256];
    __syncthreads();
    for (int s = 0; s < n; s++) {
        int j = idx[(size_t)row * SCAP + s];
        const float* b = Bmat + (size_t)j * DD;
        float p = 0.f;
#pragma unroll
        for (int k = 0; k < 4; k++) p += a[t + k * 256] * b[t + k * 256];
#pragma unroll
        for (int o = 16; o; o >>= 1) p += __shfl_xor_sync(0xffffffffu, p, o);
        if (lane == 0) red[w] = p;
        __syncthreads();
        if (t == 0) xs[s] = red[0] + red[1] + red[2] + red[3] + red[4] + red[5] + red[6] + red[7];
        __syncthreads();
    }
    if (t == 0) {
        float Mapp = gM[row], Sapp = gS[row];
        float Mn = -1e30f;
        for (int s = 0; s < n; s++) Mn = fmaxf(Mn, xs[s]);
        float S = Sapp * __expf(Mapp - Mn);
        for (int s = 0; s < n; s++) {
            int j = idx[(size_t)row * SCAP + s];
            float xa = rawIsRow ? __half2float(rawp[(size_t)row * rawPitch + j])
                                : __half2float(rawp[(size_t)j * rawPitch + row]);
            S += __expf(xs[s] - Mn) - __expf(xa - Mn);
        }
        float inv = 1.0f / S;
        for (int s = 0; s < n; s++) wl[s] = __expf(xs[s] - Mn) * inv;
    }
    __syncthreads();

    float a0 = 0.f, a1 = 0.f, a2 = 0.f, a3 = 0.f;
    for (int s = 0; s < n; s++) {
        int j = idx[(size_t)row * SCAP + s];
        float wv = wl[s];
        float4 v = *reinterpret_cast<const float4*>(Bmat + (size_t)j * DD + t * 4);
        a0 += wv * v.x; a1 += wv * v.y; a2 += wv * v.z; a3 += wv * v.w;
    }
    __half2* d = reinterpret_cast<__half2*>(att + (size_t)row * DD + t * 4);
    d[0] = __floats2half2_rn(a0, a1);
    d[1] = __floats2half2_rn(a2, a3);
}

// ======================= column sums of fp16 att -> sumv =======================
__global__ void colsum_kernel(const __half* __restrict__ att, float* __restrict__ sumv)
{
    int lane = threadIdx.x & 31, w = threadIdx.x >> 5;
    int col = blockIdx.x * 32 + lane;
    float s = 0.f;
#pragma unroll 8
    for (int r = 0; r < 1024; r++)
        s += __half2float(att[(size_t)(w * 1024 + r) * DD + col]);
    __shared__ float sh[8][33];
    sh[w][lane] = s;
    __syncthreads();
    if (threadIdx.x < 32) {
        float t = 0.f;
#pragma unroll
        for (int q = 0; q < 8; q++) t += sh[q][threadIdx.x];
        sumv[blockIdx.x * 32 + threadIdx.x] = t;
    }
}

// ======================= prep: fp32 -> fp16 cast (row-padded) =======================
__global__ void cast_kernel(const float* __restrict__ src, __half* __restrict__ dh,
                            int R, int C, int Rpad)
{
    int idx = blockIdx.x * 256 + threadIdx.x;
    if (idx >= Rpad * C) return;
    int r = idx / C;
    float v = (r < R) ? src[idx] : 0.f;
    dh[idx] = __float2half_rn(v);
}

// ======================= finalize =======================
__global__ void finalize_kernel(const float* __restrict__ Wf1, const float* __restrict__ bf1,
                                const float* __restrict__ Wf2, const float* __restrict__ bf2,
                                float* __restrict__ out)
{
    int g = blockIdx.x * 8 + (threadIdx.x >> 5);
    int lane = threadIdx.x & 31;
    const float inv = 1.0f / 8192.0f;
    if (g < FF) {
        const float* w = Wf1 + (size_t)g * DD;
        float d = 0.f;
        for (int l = lane; l < DD; l += 32) d += w[l] * g_sumv2[l];
#pragma unroll
        for (int o = 16; o; o >>= 1) d += __shfl_xor_sync(0xffffffffu, d, o);
        if (lane == 0) {
            float filt = 1.0f / (1.0f + __expf(-(d * inv + bf1[g])));
            float t = 0.f;
#pragma unroll
            for (int b = 0; b < 32; b++) t += g_tpart1[g * 32 + b];
            out[g] = t * inv * filt;
        }
    } else if (g < 2 * FF) {
        int f = g - FF;
        const float* w = Wf2 + (size_t)f * DD;
        float d = 0.f;
        for (int l = lane; l < DD; l += 32) d += w[l] * g_sumv1[l];
#pragma unroll
        for (int o = 16; o; o >>= 1) d += __shfl_xor_sync(0xffffffffu, d, o);
        if (lane == 0) {
            float filt = 1.0f / (1.0f + __expf(-(d * inv + bf2[f])));
            float t = 0.f;
#pragma unroll
            for (int b = 0; b < 32; b++) t += g_tpart2[f * 32 + b];
            out[FF + f] = t * inv * filt;
        }
    }
}

// ======================= launch =======================
extern "C" void kernel_launch(void* const* d_in, const int* in_sizes, int n_in,
                              void* d_out, int out_size)
{
    const float* m1  = (const float*)d_in[0];
    const float* m2  = (const float*)d_in[1];
    const float* Wf1 = (const float*)d_in[2];
    const float* bf1 = (const float*)d_in[3];
    const float* Wf2 = (const float*)d_in[4];
    const float* bf2 = (const float*)d_in[5];
    const float* W1  = (const float*)d_in[6];
    const float* b1  = (const float*)d_in[7];
    const float* W2  = (const float*)d_in[8];
    const float* b2  = (const float*)d_in[9];
    float* out = (float*)d_out;

    float *tpart1, *tpart2, *rpm, *rps, *cpm, *cps, *sumv1, *sumv2;
    float *rmax, *rsum, *cmax, *csum;
    int *sel2i, *sel2c, *sel1i, *sel1c;
    __half *rawh, *m1h, *m2h, *att1h, *att2h, *w1h, *w2h;
    cudaGetSymbolAddress((void**)&rawh,  g_rawh);
    cudaGetSymbolAddress((void**)&m1h,   g_m1h);
    cudaGetSymbolAddress((void**)&m2h,   g_m2h);
    cudaGetSymbolAddress((void**)&att1h, g_att1h);
    cudaGetSymbolAddress((void**)&att2h, g_att2h);
    cudaGetSymbolAddress((void**)&w1h,   g_w1h);
    cudaGetSymbolAddress((void**)&w2h,   g_w2h);
    cudaGetSymbolAddress((void**)&tpart1, g_tpart1);
    cudaGetSymbolAddress((void**)&tpart2, g_tpart2);
    cudaGetSymbolAddress((void**)&rpm, g_rpm);
    cudaGetSymbolAddress((void**)&rps, g_rps);
    cudaGetSymbolAddress((void**)&cpm, g_cpm);
    cudaGetSymbolAddress((void**)&cps, g_cps);
    cudaGetSymbolAddress((void**)&sel2i, g_sel2_idx);
    cudaGetSymbolAddress((void**)&sel2c, g_sel2_cnt);
    cudaGetSymbolAddress((void**)&sel1i, g_sel1_idx);
    cudaGetSymbolAddress((void**)&sel1c, g_sel1_cnt);
    cudaGetSymbolAddress((void**)&sumv1, g_sumv1);
    cudaGetSymbolAddress((void**)&sumv2, g_sumv2);
    cudaGetSymbolAddress((void**)&rmax, g_rmax);
    cudaGetSymbolAddress((void**)&rsum, g_rsum);
    cudaGetSymbolAddress((void**)&cmax, g_cmax);
    cudaGetSymbolAddress((void**)&csum, g_csum);

    cudaFuncSetAttribute(hgemm<0>, cudaFuncAttributeMaxDynamicSharedMemorySize, 92160);
    cudaFuncSetAttribute(hgemm<2>, cudaFuncAttributeMaxDynamicSharedMemorySize, 92160);

    // 0) prep: cast inputs to fp16
    cast_kernel<<<(N1V * DD + 255) / 256, 256>>>(m1, m1h, N1V, DD, N1V);
    cast_kernel<<<(N2V * DD + 255) / 256, 256>>>(m2, m2h, N2V, DD, N2V);
    cast_kernel<<<(FPAD * DD + 255) / 256, 256>>>(W1, w1h, FF, DD, FPAD);
    cast_kernel<<<(FPAD * DD + 255) / 256, 256>>>(W2, w2h, FF, DD, FPAD);

    // 1) approx raw = m1 @ m2^T (fp16 store), fused softmax stat partials on rounded values
    hgemm<0><<<dim3(N2V / 256, N1V / 128), 256, 92160>>>(
        m1h, m2h, nullptr, nullptr, rawh, N2V, DD, DD / 32, N1V,
        nullptr, nullptr, nullptr, nullptr, rpm, rps, cpm, cps);

    // 2) merge approx stats (M, S)
    stats_merge_kernel<<<(N1V + N2V) / 8, 256>>>();

    // 3) threshold selection (20-nat margin)
    select_rows_kernel<<<N1V, 256>>>();
    select_cols_kernel<<<N2V / 32, 256>>>();

    // 4) refine + gather fused (exact logits, exact softmax, fp32 gather -> fp16 att)
    refine_gather_kernel<<<N1V, 256>>>(m1, m2, sel2c, sel2i, rmax, rsum, rawh, N2V, 1, att2h);
    refine_gather_kernel<<<N2V, 256>>>(m2, m1, sel1c, sel1i, cmax, csum, rawh, N2V, 0, att1h);

    // 5) column sums for the filter path
    colsum_kernel<<<DD / 32, 256>>>(att1h, sumv1);
    colsum_kernel<<<DD / 32, 256>>>(att2h, sumv2);

    // 6) transform GEMMs merged into one launch (z selects W1/att1 vs W2/att2)
    hgemm<2><<<dim3(N2V / 256, FPAD / 128, 2), 256, 92160>>>(
        w1h, att1h, w2h, att2h, nullptr, 0, DD, DD / 32, FF,
        b1, tpart1, b2, tpart2, nullptr, nullptr, nullptr, nullptr);

    // 7) filters + outputs
    finalize_kernel<<<200, 256>>>(Wf1, bf1, Wf2, bf2, out);
}

// round 15
// speedup vs baseline: 1.5327x; 1.0518x over previous
#include <cuda_runtime.h>
#include <cuda_fp16.h>
#include <cuda_fp8.h>
#include <math.h>
#include <stdint.h>
#include <stddef.h>

#define N1V 8192
#define N2V 8192
#define DD  1024
#define FF  800
#define FPAD 896
#define SCAP 512
#define STHR 20.0f

// ======================= scratch (device globals) =======================
__device__ __half  g_rawh[(size_t)N1V * N2V];    // approx logits fp16
__device__ uint8_t g_m1q[(size_t)N1V * DD];      // m1 e4m3
__device__ uint8_t g_m2q[(size_t)N2V * DD];      // m2 e4m3
__device__ __half g_att1h[(size_t)N2V * DD];
__device__ __half g_att2h[(size_t)N1V * DD];
__device__ __half g_w1h[FPAD * DD];
__device__ __half g_w2h[FPAD * DD];
__device__ float g_rmax[N1V], g_rsum[N1V];
__device__ float g_cmax[N2V], g_csum[N2V];
__device__ float g_rpm[(size_t)N1V * 32], g_rps[(size_t)N1V * 32];
__device__ float g_cpm[(size_t)N2V * 64], g_cps[(size_t)N2V * 64];
__device__ int   g_sel2_idx[(size_t)N1V * SCAP];
__device__ int   g_sel2_cnt[N1V];
__device__ int   g_sel1_idx[(size_t)N2V * SCAP];
__device__ int   g_sel1_cnt[N2V];
__device__ float g_sumv1[DD], g_sumv2[DD];
__device__ float g_tpart1[FPAD * 32], g_tpart2[FPAD * 32];

// ======================= asm helpers =======================
static __device__ __forceinline__ uint32_t smem_u32(const void* p) {
    uint32_t a;
    asm("{ .reg .u64 t; cvta.to.shared.u64 t, %1; cvt.u32.u64 %0, t; }" : "=r"(a) : "l"(p));
    return a;
}
static __device__ __forceinline__ uint64_t gaddr(const void* p) {
    uint64_t a;
    asm("cvta.to.global.u64 %0, %1;" : "=l"(a) : "l"(p));
    return a;
}
static __device__ __forceinline__ void cpa16(uint32_t dst, uint64_t src) {
    asm volatile("cp.async.cg.shared.global [%0], [%1], 16;" :: "r"(dst), "l"(src));
}
static __device__ __forceinline__ void ldsm_x4(uint32_t& r0, uint32_t& r1, uint32_t& r2, uint32_t& r3, uint32_t addr) {
    asm volatile("ldmatrix.sync.aligned.m8n8.x4.shared.b16 {%0,%1,%2,%3}, [%4];"
                 : "=r"(r0), "=r"(r1), "=r"(r2), "=r"(r3) : "r"(addr));
}
static __device__ __forceinline__ void mma16816(float* d, const uint32_t* a, uint32_t b0, uint32_t b1) {
    asm volatile("mma.sync.aligned.m16n8k16.row.col.f32.f16.f16.f32 "
                 "{%0,%1,%2,%3}, {%4,%5,%6,%7}, {%8,%9}, {%0,%1,%2,%3};"
                 : "+f"(d[0]), "+f"(d[1]), "+f"(d[2]), "+f"(d[3])
                 : "r"(a[0]), "r"(a[1]), "r"(a[2]), "r"(a[3]), "r"(b0), "r"(b1));
}
static __device__ __forceinline__ void mmaq(float* d, const uint32_t* a, uint32_t b0, uint32_t b1) {
    asm volatile("mma.sync.aligned.m16n8k32.row.col.f32.e4m3.e4m3.f32 "
                 "{%0,%1,%2,%3}, {%4,%5,%6,%7}, {%8,%9}, {%0,%1,%2,%3};"
                 : "+f"(d[0]), "+f"(d[1]), "+f"(d[2]), "+f"(d[3])
                 : "r"(a[0]), "r"(a[1]), "r"(a[2]), "r"(a[3]), "r"(b0), "r"(b1));
}
static __device__ __forceinline__ void msmerge(float& m, float& s, float mo, float so) {
    float mn = fmaxf(m, mo);
    s = s * __expf(m - mn) + so * __expf(mo - mn);
    m = mn;
}

// ======================= fp8 raw GEMM, 128x256 block, K=64 tiles =======================
// raw = A.B^T (e4m3 operands, fp32 accum). Stores fp16 logits; computes row/col
// softmax stat partials from the ROUNDED values (consistency with refine).
// smem rows padded to 80 B (16B aligned, conflict-free). 3-stage cp.async.
__global__ void __launch_bounds__(256, 1)
hgemm8(const uint8_t* __restrict__ A8, const uint8_t* __restrict__ B8,
       __half* __restrict__ Ch, long ldw, int K, int NT,
       float* __restrict__ rpm, float* __restrict__ rps,
       float* __restrict__ cpm, float* __restrict__ cps)
{
    extern __shared__ char smem[];
    const uint32_t sbase = smem_u32(smem);
    const int STGSZ = 30720;   // A 128*80=10240 + B 256*80=20480
    const int tid = threadIdx.x, lane = tid & 31, wid = tid >> 5;
    const int warp_m = wid & 1;
    const int warp_n = wid >> 1;
    const int m0 = blockIdx.y * 128;
    const int n0 = blockIdx.x * 256;

    const int arow = lane & 15, acolB = (lane >> 4) << 4;              // byte offsets
    const int brow = (lane & 7) + ((lane & 16) >> 1), bcolB = (lane & 8) << 1;

    const uint64_t gA = gaddr(A8);
    const uint64_t gB = gaddr(B8);

    float acc[4][8][4];
#pragma unroll
    for (int i = 0; i < 4; i++)
#pragma unroll
        for (int j = 0; j < 8; j++)
#pragma unroll
            for (int k = 0; k < 4; k++) acc[i][j][k] = 0.f;

    auto load_stage = [&](int kt, int bufi) {
        const int k0 = kt * 64;
        uint32_t sb = sbase + bufi * STGSZ;
#pragma unroll
        for (int i = 0; i < 2; i++) {              // A: 128 rows x 64B = 512 chunks
            int idx = tid + i * 256;
            int r = idx >> 2, c = (idx & 3) << 4;
            cpa16(sb + (uint32_t)(r * 80 + c), gA + (uint64_t)(m0 + r) * K + k0 + c);
        }
#pragma unroll
        for (int i = 0; i < 4; i++) {              // B: 256 rows x 64B = 1024 chunks
            int idx = tid + i * 256;
            int r = idx >> 2, c = (idx & 3) << 4;
            cpa16(sb + 10240 + (uint32_t)(r * 80 + c), gB + (uint64_t)(n0 + r) * K + k0 + c);
        }
        asm volatile("cp.async.commit_group;" ::: "memory");
    };

    load_stage(0, 0);
    load_stage(1, 1);
    for (int t = 0; t < NT; t++) {
        if (t + 2 < NT) {
            load_stage(t + 2, (t + 2) % 3);
            asm volatile("cp.async.wait_group 2;" ::: "memory");
        } else if (t + 1 < NT) {
            asm volatile("cp.async.wait_group 1;" ::: "memory");
        } else {
            asm volatile("cp.async.wait_group 0;" ::: "memory");
        }
        __syncthreads();
        uint32_t sa = sbase + (t % 3) * STGSZ;
#pragma unroll
        for (int ks = 0; ks < 2; ks++) {
            uint32_t ah[4][4];
#pragma unroll
            for (int mf = 0; mf < 4; mf++) {
                uint32_t addr = sa + (uint32_t)((warp_m * 64 + mf * 16 + arow) * 80 + ks * 32 + acolB);
                ldsm_x4(ah[mf][0], ah[mf][1], ah[mf][2], ah[mf][3], addr);
            }
            uint32_t bh[4][4];
#pragma unroll
            for (int nf2 = 0; nf2 < 4; nf2++) {
                uint32_t addr = sa + 10240 + (uint32_t)((warp_n * 64 + nf2 * 16 + brow) * 80 + ks * 32 + bcolB);
                ldsm_x4(bh[nf2][0], bh[nf2][1], bh[nf2][2], bh[nf2][3], addr);
            }
#pragma unroll
            for (int mf = 0; mf < 4; mf++)
#pragma unroll
                for (int nf = 0; nf < 8; nf++) {
                    int nf2 = nf >> 1, o = (nf & 1) * 2;
                    mmaq(acc[mf][nf], ah[mf], bh[nf2][o], bh[nf2][o + 1]);
                }
        }
        __syncthreads();
    }

    const int gr = lane >> 2, q = lane & 3;
    // ---- round to fp16, store, replace acc with rounded values ----
#pragma unroll
    for (int mf = 0; mf < 4; mf++)
#pragma unroll
        for (int nf = 0; nf < 8; nf++) {
            int row = m0 + warp_m * 64 + mf * 16 + gr;
            int col = n0 + warp_n * 64 + nf * 8 + q * 2;
            __half2 h01 = __floats2half2_rn(acc[mf][nf][0], acc[mf][nf][1]);
            __half2 h23 = __floats2half2_rn(acc[mf][nf][2], acc[mf][nf][3]);
            *reinterpret_cast<__half2*>(Ch + (size_t)row * ldw + col)       = h01;
            *reinterpret_cast<__half2*>(Ch + (size_t)(row + 8) * ldw + col) = h23;
            float2 f01 = __half22float2(h01);
            float2 f23 = __half22float2(h23);
            acc[mf][nf][0] = f01.x; acc[mf][nf][1] = f01.y;
            acc[mf][nf][2] = f23.x; acc[mf][nf][3] = f23.y;
        }
    float rm[8], rs[8];
#pragma unroll
    for (int mf = 0; mf < 4; mf++) {
        float ma = -1e30f, mb = -1e30f;
#pragma unroll
        for (int nf = 0; nf < 8; nf++) {
            ma = fmaxf(ma, fmaxf(acc[mf][nf][0], acc[mf][nf][1]));
            mb = fmaxf(mb, fmaxf(acc[mf][nf][2], acc[mf][nf][3]));
        }
        float sa = 0.f, sb = 0.f;
#pragma unroll
        for (int nf = 0; nf < 8; nf++) {
            sa += __expf(acc[mf][nf][0] - ma) + __expf(acc[mf][nf][1] - ma);
            sb += __expf(acc[mf][nf][2] - mb) + __expf(acc[mf][nf][3] - mb);
        }
        rm[2 * mf] = ma;  rs[2 * mf] = sa;
        rm[2 * mf + 1] = mb;  rs[2 * mf + 1] = sb;
    }
#pragma unroll
    for (int o = 1; o < 4; o <<= 1)
#pragma unroll
        for (int k = 0; k < 8; k++) {
            float mo = __shfl_xor_sync(0xffffffffu, rm[k], o);
            float so = __shfl_xor_sync(0xffffffffu, rs[k], o);
            msmerge(rm[k], rs[k], mo, so);
        }
    float cm[16], cs[16];
#pragma unroll
    for (int nf = 0; nf < 8; nf++)
#pragma unroll
        for (int b = 0; b < 2; b++) {
            int i = nf * 2 + b;
            float mv = -1e30f;
#pragma unroll
            for (int mf = 0; mf < 4; mf++)
                mv = fmaxf(mv, fmaxf(acc[mf][nf][b], acc[mf][nf][b + 2]));
            float sv = 0.f;
#pragma unroll
            for (int mf = 0; mf < 4; mf++)
                sv += __expf(acc[mf][nf][b] - mv) + __expf(acc[mf][nf][b + 2] - mv);
            cm[i] = mv;  cs[i] = sv;
        }
#pragma unroll
    for (int o = 4; o < 32; o <<= 1)
#pragma unroll
        for (int k = 0; k < 16; k++) {
            float mo = __shfl_xor_sync(0xffffffffu, cm[k], o);
            float so = __shfl_xor_sync(0xffffffffu, cs[k], o);
            msmerge(cm[k], cs[k], mo, so);
        }
    float* rowm  = reinterpret_cast<float*>(smem);
    float* rows_ = rowm + 512;
    float* colm  = rows_ + 512;
    float* cols_ = colm + 512;
    if (q == 0) {
#pragma unroll
        for (int mf = 0; mf < 4; mf++) {
            int lr = warp_m * 64 + mf * 16 + gr;
            rowm [lr * 4 + warp_n] = rm[2 * mf];
            rows_[lr * 4 + warp_n] = rs[2 * mf];
            rowm [(lr + 8) * 4 + warp_n] = rm[2 * mf + 1];
            rows_[(lr + 8) * 4 + warp_n] = rs[2 * mf + 1];
        }
    }
    if (lane < 4) {
#pragma unroll
        for (int nf = 0; nf < 8; nf++)
#pragma unroll
            for (int b = 0; b < 2; b++) {
                int cc = warp_n * 64 + nf * 8 + lane * 2 + b;
                colm [warp_m * 256 + cc] = cm[nf * 2 + b];
                cols_[warp_m * 256 + cc] = cs[nf * 2 + b];
            }
    }
    __syncthreads();
    if (tid < 128) {
        float M = rowm[tid * 4], S = rows_[tid * 4];
#pragma unroll
        for (int w = 1; w < 4; w++) msmerge(M, S, rowm[tid * 4 + w], rows_[tid * 4 + w]);
        rpm[(size_t)(m0 + tid) * 32 + blockIdx.x] = M;
        rps[(size_t)(m0 + tid) * 32 + blockIdx.x] = S;
    }
    {
        float M = colm[tid], S = cols_[tid];
        msmerge(M, S, colm[256 + tid], cols_[256 + tid]);
        cpm[(size_t)(n0 + tid) * 64 + blockIdx.y] = M;
        cps[(size_t)(n0 + tid) * 64 + blockIdx.y] = S;
    }
}

// ======================= fp16 transform GEMM (merged z=2), tanh+rowsum epilogue ======
__global__ void __launch_bounds__(256, 1)
tgemm(const __half* __restrict__ Ah, const __half* __restrict__ Bh,
      const __half* __restrict__ Ah2, const __half* __restrict__ Bh2,
      int K, int NT, int Mvalid,
      const float* __restrict__ bias, float* __restrict__ tpart,
      const float* __restrict__ bias2, float* __restrict__ tpart2)
{
    extern __shared__ char smem[];
    const uint32_t sbase = smem_u32(smem);
    const int STGSZ = 30720;
    const int tid = threadIdx.x, lane = tid & 31, wid = tid >> 5;
    const int warp_m = wid & 1;
    const int warp_n = wid >> 1;
    const int m0 = blockIdx.y * 128;
    const int n0 = blockIdx.x * 256;

    const __half* Aop = blockIdx.z ? Ah2 : Ah;
    const __half* Bop = blockIdx.z ? Bh2 : Bh;

    const int arow = lane & 15, acol = (lane >> 4) << 3;
    const int brow = (lane & 7) + ((lane & 16) >> 1);
    const int bcol = lane & 8;

    const uint64_t gAh = gaddr(Aop);
    const uint64_t gBh = gaddr(Bop);

    float acc[4][8][4];
#pragma unroll
    for (int i = 0; i < 4; i++)
#pragma unroll
        for (int j = 0; j < 8; j++)
#pragma unroll
            for (int k = 0; k < 4; k++) acc[i][j][k] = 0.f;

    auto load_stage = [&](int kt, int bufi) {
        const int k0 = kt * 32;
        uint32_t sb = sbase + bufi * STGSZ;
#pragma unroll
        for (int i = 0; i < 2; i++) {
            int idx = tid + i * 256;
            int r = idx >> 2, c = (idx & 3) << 3;
            cpa16(sb + (uint32_t)(r * 40 + c) * 2, gAh + ((uint64_t)(m0 + r) * K + k0 + c) * 2);
        }
#pragma unroll
        for (int i = 0; i < 4; i++) {
            int idx = tid + i * 256;
            int r = idx >> 2, c = (idx & 3) << 3;
            cpa16(sb + 10240 + (uint32_t)(r * 40 + c) * 2, gBh + ((uint64_t)(n0 + r) * K + k0 + c) * 2);
        }
        asm volatile("cp.async.commit_group;" ::: "memory");
    };

    load_stage(0, 0);
    load_stage(1, 1);
    for (int t = 0; t < NT; t++) {
        if (t + 2 < NT) {
            load_stage(t + 2, (t + 2) % 3);
            asm volatile("cp.async.wait_group 2;" ::: "memory");
        } else if (t + 1 < NT) {
            asm volatile("cp.async.wait_group 1;" ::: "memory");
        } else {
            asm volatile("cp.async.wait_group 0;" ::: "memory");
        }
        __syncthreads();
        uint32_t sa = sbase + (t % 3) * STGSZ;
#pragma unroll
        for (int ks = 0; ks < 2; ks++) {
            uint32_t ah[4][4];
#pragma unroll
            for (int mf = 0; mf < 4; mf++) {
                uint32_t addr = sa + (uint32_t)((warp_m * 64 + mf * 16 + arow) * 40 + ks * 16 + acol) * 2;
                ldsm_x4(ah[mf][0], ah[mf][1], ah[mf][2], ah[mf][3], addr);
            }
            uint32_t bh[4][4];
#pragma unroll
            for (int nf2 = 0; nf2 < 4; nf2++) {
                uint32_t addr = sa + 10240 + (uint32_t)((warp_n * 64 + nf2 * 16 + brow) * 40 + ks * 16 + bcol) * 2;
                ldsm_x4(bh[nf2][0], bh[nf2][1], bh[nf2][2], bh[nf2][3], addr);
            }
#pragma unroll
            for (int mf = 0; mf < 4; mf++)
#pragma unroll
                for (int nf = 0; nf < 8; nf++) {
                    int nf2 = nf >> 1, o = (nf & 1) * 2;
                    mma16816(acc[mf][nf], ah[mf], bh[nf2][o], bh[nf2][o + 1]);
                }
        }
        __syncthreads();
    }

    const int gr = lane >> 2, q = lane & 3;
    const float* bs = blockIdx.z ? bias2 : bias;
    float* tp = blockIdx.z ? tpart2 : tpart;
    float rsum[8];
#pragma unroll
    for (int k = 0; k < 8; k++) rsum[k] = 0.f;
#pragma unroll
    for (int mf = 0; mf < 4; mf++) {
        int row = m0 + warp_m * 64 + mf * 16 + gr;
        float bj0 = (row < Mvalid)     ? bs[row]     : 0.f;
        float bj1 = (row + 8 < Mvalid) ? bs[row + 8] : 0.f;
#pragma unroll
        for (int nf = 0; nf < 8; nf++) {
            rsum[mf * 2]     += tanhf(acc[mf][nf][0] + bj0) + tanhf(acc[mf][nf][1] + bj0);
            rsum[mf * 2 + 1] += tanhf(acc[mf][nf][2] + bj1) + tanhf(acc[mf][nf][3] + bj1);
        }
    }
#pragma unroll
    for (int o = 1; o < 4; o <<= 1)
#pragma unroll
        for (int k = 0; k < 8; k++) rsum[k] += __shfl_xor_sync(0xffffffffu, rsum[k], o);
    __syncthreads();
    float* red = reinterpret_cast<float*>(smem);
    if (q == 0) {
#pragma unroll
        for (int mf = 0; mf < 4; mf++) {
            int lr = warp_m * 64 + mf * 16 + gr;
            red[lr * 4 + warp_n]       = rsum[mf * 2];
            red[(lr + 8) * 4 + warp_n] = rsum[mf * 2 + 1];
        }
    }
    __syncthreads();
    if (tid < 128) {
        float s = red[tid * 4] + red[tid * 4 + 1] + red[tid * 4 + 2] + red[tid * 4 + 3];
        int f = m0 + tid;
        if (f < Mvalid) tp[(size_t)f * gridDim.x + blockIdx.x] = s;
    }
}

// ======================= merge softmax stat partials =======================
__global__ void stats_merge_kernel()
{
    int g = blockIdx.x * 8 + (threadIdx.x >> 5);
    int lane = threadIdx.x & 31;
    if (g < N1V) {
        float m = g_rpm[(size_t)g * 32 + lane];
        float s = g_rps[(size_t)g * 32 + lane];
#pragma unroll
        for (int o = 16; o; o >>= 1) {
            float mo = __shfl_xor_sync(0xffffffffu, m, o);
            float so = __shfl_xor_sync(0xffffffffu, s, o);
            msmerge(m, s, mo, so);
        }
        if (lane == 0) { g_rmax[g] = m; g_rsum[g] = s; }
    } else {
        int c = g - N1V;
        float m = g_cpm[(size_t)c * 64 + lane];
        float s = g_cps[(size_t)c * 64 + lane];
        msmerge(m, s, g_cpm[(size_t)c * 64 + 32 + lane], g_cps[(size_t)c * 64 + 32 + lane]);
#pragma unroll
        for (int o = 16; o; o >>= 1) {
            float mo = __shfl_xor_sync(0xffffffffu, m, o);
            float so = __shfl_xor_sync(0xffffffffu, s, o);
            msmerge(m, s, mo, so);
        }
        if (lane == 0) { g_cmax[c] = m; g_csum[c] = s; }
    }
}

// ======================= selection: rows (alpha2) =======================
__global__ void select_rows_kernel()
{
    int row = blockIdx.x;
    int t = threadIdx.x, lane = t & 31, w = t >> 5;
    const __half* r = g_rawh + (size_t)row * N2V;
    float thr = g_rmax[row] - STHR;
    int base = t * 32;
    uint32_t mask = 0;
    int c = 0;
#pragma unroll 8
    for (int k = 0; k < 32; k++) {
        bool p = __half2float(r[base + k]) > thr;
        mask |= (uint32_t)p << k;
        c += p ? 1 : 0;
    }
    int v = c;
#pragma unroll
    for (int o = 1; o < 32; o <<= 1) {
        int u = __shfl_up_sync(0xffffffffu, v, o);
        if (lane >= o) v += u;
    }
    __shared__ int wt[8];
    if (lane == 31) wt[w] = v;
    __syncthreads();
    int woff = 0;
#pragma unroll
    for (int s = 0; s < 8; s++) if (s < w) woff += wt[s];
    int off = woff + v - c;
    while (mask) {
        int k = __ffs(mask) - 1;
        mask &= mask - 1;
        if (off < SCAP) g_sel2_idx[(size_t)row * SCAP + off] = base + k;
        off++;
    }
    if (t == 0) {
        int total = wt[0] + wt[1] + wt[2] + wt[3] + wt[4] + wt[5] + wt[6] + wt[7];
        g_sel2_cnt[row] = total < SCAP ? total : SCAP;
    }
}

// ======================= selection: cols (alpha1) =======================
__global__ void select_cols_kernel()
{
    __shared__ uint32_t masks[256][32];
    __shared__ int scnt[8][32];
    int lane = threadIdx.x & 31, w = threadIdx.x >> 5;
    int col = blockIdx.x * 32 + lane;
    float thr = g_cmax[col] - STHR;
    int r0 = w * 1024;
    int c = 0;
    for (int word = 0; word < 32; word++) {
        uint32_t m = 0;
#pragma unroll 8
        for (int b = 0; b < 32; b++) {
            bool p = __half2float(g_rawh[(size_t)(r0 + word * 32 + b) * N2V + col]) > thr;
            m |= (uint32_t)p << b;
            c += p ? 1 : 0;
        }
        masks[threadIdx.x][word] = m;
    }
    scnt[w][lane] = c;
    __syncthreads();
    int off = 0, total = 0;
#pragma unroll
    for (int s = 0; s < 8; s++) {
        if (s < w) off += scnt[s][lane];
        total += scnt[s][lane];
    }
    for (int word = 0; word < 32; word++) {
        uint32_t m = masks[threadIdx.x][word];
        while (m) {
            int b = __ffs(m) - 1;
            m &= m - 1;
            if (off < SCAP) g_sel1_idx[(size_t)col * SCAP + off] = r0 + word * 32 + b;
            off++;
        }
    }
    if (w == 0) g_sel1_cnt[col] = total < SCAP ? total : SCAP;
}

// ======================= refine + gather (fused) =======================
__global__ void refine_gather_kernel(const float* __restrict__ Arow, const float* __restrict__ Bmat,
                                     const int* __restrict__ cnt, const int* __restrict__ idx,
                                     const float* __restrict__ gM, const float* __restrict__ gS,
                                     const __half* __restrict__ rawp, long rawPitch, int rawIsRow,
                                     __half* __restrict__ att)
{
    __shared__ float a[DD];
    __shared__ float xs[SCAP];
    __shared__ float wl[SCAP];
    __shared__ float red[8];
    int row = blockIdx.x;
    int t = threadIdx.x, lane = t & 31, w = t >> 5;
    int n = cnt[row];
#pragma unroll
    for (int k = 0; k < 4; k++) a[t + k * 256] = Arow[(size_t)row * DD + t + k * 256];
    __syncthreads();
    for (int s = 0; s < n; s++) {
        int j = idx[(size_t)row * SCAP + s];
        const float* b = Bmat + (size_t)j * DD;
        float p = 0.f;
#pragma unroll
        for (int k = 0; k < 4; k++) p += a[t + k * 256] * b[t + k * 256];
#pragma unroll
        for (int o = 16; o; o >>= 1) p += __shfl_xor_sync(0xffffffffu, p, o);
        if (lane == 0) red[w] = p;
        __syncthreads();
        if (t == 0) xs[s] = red[0] + red[1] + red[2] + red[3] + red[4] + red[5] + red[6] + red[7];
        __syncthreads();
    }
    if (t == 0) {
        float Mapp = gM[row], Sapp = gS[row];
        float Mn = -1e30f;
        for (int s = 0; s < n; s++) Mn = fmaxf(Mn, xs[s]);
        Mn = fmaxf(Mn, Mapp);
        float S = Sapp * __expf(Mapp - Mn);
        for (int s = 0; s < n; s++) {
            int j = idx[(size_t)row * SCAP + s];
            float xa = rawIsRow ? __half2float(rawp[(size_t)row * rawPitch + j])
                                : __half2float(rawp[(size_t)j * rawPitch + row]);
            S += __expf(xs[s] - Mn) - __expf(xa - Mn);
        }
        float inv = 1.0f / S;
        for (int s = 0; s < n; s++) wl[s] = __expf(xs[s] - Mn) * inv;
    }
    __syncthreads();

    float a0 = 0.f, a1 = 0.f, a2 = 0.f, a3 = 0.f;
    for (int s = 0; s < n; s++) {
        int j = idx[(size_t)row * SCAP + s];
        float wv = wl[s];
        float4 v = *reinterpret_cast<const float4*>(Bmat + (size_t)j * DD + t * 4);
        a0 += wv * v.x; a1 += wv * v.y; a2 += wv * v.z; a3 += wv * v.w;
    }
    __half2* d = reinterpret_cast<__half2*>(att + (size_t)row * DD + t * 4);
    d[0] = __floats2half2_rn(a0, a1);
    d[1] = __floats2half2_rn(a2, a3);
}

// ======================= column sums of fp16 att -> sumv =======================
__global__ void colsum_kernel(const __half* __restrict__ att, float* __restrict__ sumv)
{
    int lane = threadIdx.x & 31, w = threadIdx.x >> 5;
    int col = blockIdx.x * 32 + lane;
    float s = 0.f;
#pragma unroll 8
    for (int r = 0; r < 1024; r++)
        s += __half2float(att[(size_t)(w * 1024 + r) * DD + col]);
    __shared__ float sh[8][33];
    sh[w][lane] = s;
    __syncthreads();
    if (threadIdx.x < 32) {
        float t = 0.f;
#pragma unroll
        for (int q = 0; q < 8; q++) t += sh[q][threadIdx.x];
        sumv[blockIdx.x * 32 + threadIdx.x] = t;
    }
}

// ======================= prep casts =======================
__global__ void cast_kernel(const float* __restrict__ src, __half* __restrict__ dh,
                            int R, int C, int Rpad)
{
    int idx = blockIdx.x * 256 + threadIdx.x;
    if (idx >= Rpad * C) return;
    int r = idx / C;
    float v = (r < R) ? src[idx] : 0.f;
    dh[idx] = __float2half_rn(v);
}

__global__ void cast8_kernel(const float* __restrict__ src, uint8_t* __restrict__ dst, int n)
{
    int i = blockIdx.x * 256 + threadIdx.x;
    if (i >= n) return;
    __nv_fp8_e4m3 v(src[i]);
    dst[i] = *reinterpret_cast<uint8_t*>(&v);
}

// ======================= finalize =======================
__global__ void finalize_kernel(const float* __restrict__ Wf1, const float* __restrict__ bf1,
                                const float* __restrict__ Wf2, const float* __restrict__ bf2,
                                float* __restrict__ out)
{
    int g = blockIdx.x * 8 + (threadIdx.x >> 5);
    int lane = threadIdx.x & 31;
    const float inv = 1.0f / 8192.0f;
    if (g < FF) {
        const float* w = Wf1 + (size_t)g * DD;
        float d = 0.f;
        for (int l = lane; l < DD; l += 32) d += w[l] * g_sumv2[l];
#pragma unroll
        for (int o = 16; o; o >>= 1) d += __shfl_xor_sync(0xffffffffu, d, o);
        if (lane == 0) {
            float filt = 1.0f / (1.0f + __expf(-(d * inv + bf1[g])));
            float t = 0.f;
#pragma unroll
            for (int b = 0; b < 32; b++) t += g_tpart1[g * 32 + b];
            out[g] = t * inv * filt;
        }
    } else if (g < 2 * FF) {
        int f = g - FF;
        const float* w = Wf2 + (size_t)f * DD;
        float d = 0.f;
        for (int l = lane; l < DD; l += 32) d += w[l] * g_sumv1[l];
#pragma unroll
        for (int o = 16; o; o >>= 1) d += __shfl_xor_sync(0xffffffffu, d, o);
        if (lane == 0) {
            float filt = 1.0f / (1.0f + __expf(-(d * inv + bf2[f])));
            float t = 0.f;
#pragma unroll
            for (int b = 0; b < 32; b++) t += g_tpart2[f * 32 + b];
            out[FF + f] = t * inv * filt;
        }
    }
}

// ======================= launch =======================
extern "C" void kernel_launch(void* const* d_in, const int* in_sizes, int n_in,
                              void* d_out, int out_size)
{
    const float* m1  = (const float*)d_in[0];
    const float* m2  = (const float*)d_in[1];
    const float* Wf1 = (const float*)d_in[2];
    const float* bf1 = (const float*)d_in[3];
    const float* Wf2 = (const float*)d_in[4];
    const float* bf2 = (const float*)d_in[5];
    const float* W1  = (const float*)d_in[6];
    const float* b1  = (const float*)d_in[7];
    const float* W2  = (const float*)d_in[8];
    const float* b2  = (const float*)d_in[9];
    float* out = (float*)d_out;

    float *tpart1, *tpart2, *rpm, *rps, *cpm, *cps, *sumv1, *sumv2;
    float *rmax, *rsum, *cmax, *csum;
    int *sel2i, *sel2c, *sel1i, *sel1c;
    uint8_t *m1q, *m2q;
    __half *rawh, *att1h, *att2h, *w1h, *w2h;
    cudaGetSymbolAddress((void**)&rawh,  g_rawh);
    cudaGetSymbolAddress((void**)&m1q,   g_m1q);
    cudaGetSymbolAddress((void**)&m2q,   g_m2q);
    cudaGetSymbolAddress((void**)&att1h, g_att1h);
    cudaGetSymbolAddress((void**)&att2h, g_att2h);
    cudaGetSymbolAddress((void**)&w1h,   g_w1h);
    cudaGetSymbolAddress((void**)&w2h,   g_w2h);
    cudaGetSymbolAddress((void**)&tpart1, g_tpart1);
    cudaGetSymbolAddress((void**)&tpart2, g_tpart2);
    cudaGetSymbolAddress((void**)&rpm, g_rpm);
    cudaGetSymbolAddress((void**)&rps, g_rps);
    cudaGetSymbolAddress((void**)&cpm, g_cpm);
    cudaGetSymbolAddress((void**)&cps, g_cps);
    cudaGetSymbolAddress((void**)&sel2i, g_sel2_idx);
    cudaGetSymbolAddress((void**)&sel2c, g_sel2_cnt);
    cudaGetSymbolAddress((void**)&sel1i, g_sel1_idx);
    cudaGetSymbolAddress((void**)&sel1c, g_sel1_cnt);
    cudaGetSymbolAddress((void**)&sumv1, g_sumv1);
    cudaGetSymbolAddress((void**)&sumv2, g_sumv2);
    cudaGetSymbolAddress((void**)&rmax, g_rmax);
    cudaGetSymbolAddress((void**)&rsum, g_rsum);
    cudaGetSymbolAddress((void**)&cmax, g_cmax);
    cudaGetSymbolAddress((void**)&csum, g_csum);

    cudaFuncSetAttribute(hgemm8, cudaFuncAttributeMaxDynamicSharedMemorySize, 92160);
    cudaFuncSetAttribute(tgemm,  cudaFuncAttributeMaxDynamicSharedMemorySize, 92160);

    // 0) prep: e4m3 copies of m1/m2 (raw GEMM), fp16 W
    cast8_kernel<<<(N1V * DD + 255) / 256, 256>>>(m1, m1q, N1V * DD);
    cast8_kernel<<<(N2V * DD + 255) / 256, 256>>>(m2, m2q, N2V * DD);
    cast_kernel<<<(FPAD * DD + 255) / 256, 256>>>(W1, w1h, FF, DD, FPAD);
    cast_kernel<<<(FPAD * DD + 255) / 256, 256>>>(W2, w2h, FF, DD, FPAD);

    // 1) approx raw = m1 @ m2^T, e4m3 MMA (fp16 store), fused softmax stat partials
    hgemm8<<<dim3(N2V / 256, N1V / 128), 256, 92160>>>(
        m1q, m2q, rawh, N2V, DD, DD / 64, rpm, rps, cpm, cps);

    // 2) merge approx stats (M, S)
    stats_merge_kernel<<<(N1V + N2V) / 8, 256>>>();

    // 3) threshold selection (20-nat margin; fp8 logit noise sigma~1.6 absorbed)
    select_rows_kernel<<<N1V, 256>>>();
    select_cols_kernel<<<N2V / 32, 256>>>();

    // 4) refine + gather fused (exact fp32 logits, exact softmax, fp32 gather -> fp16 att)
    refine_gather_kernel<<<N1V, 256>>>(m1, m2, sel2c, sel2i, rmax, rsum, rawh, N2V, 1, att2h);
    refine_gather_kernel<<<N2V, 256>>>(m2, m1, sel1c, sel1i, cmax, csum, rawh, N2V, 0, att1h);

    // 5) column sums for the filter path
    colsum_kernel<<<DD / 32, 256>>>(att1h, sumv1);
    colsum_kernel<<<DD / 32, 256>>>(att2h, sumv2);

    // 6) transform GEMMs merged (z selects W1/att1 vs W2/att2), fused tanh+rowsum
    tgemm<<<dim3(N2V / 256, FPAD / 128, 2), 256, 92160>>>(
        w1h, att1h, w2h, att2h, DD, DD / 32, FF, b1, tpart1, b2, tpart2);

    // 7) filters + outputs
    finalize_kernel<<<200, 256>>>(Wf1, bf1, Wf2, bf2, out);
}

// round 16
// speedup vs baseline: 1.7068x; 1.1135x over previous
#include <cuda_runtime.h>
#include <cuda_fp16.h>
#include <cuda_fp8.h>
#include <math.h>
#include <stdint.h>
#include <stddef.h>

#define N1V 8192
#define N2V 8192
#define DD  1024
#define FF  800
#define FPAD 896
#define KEEPMAX 64
#define STHR 20.0f

// ======================= scratch (device globals) =======================
__device__ __half  g_rawh[(size_t)N1V * N2V];    // approx logits fp16
__device__ uint8_t g_m1q[(size_t)N1V * DD];
__device__ uint8_t g_m2q[(size_t)N2V * DD];
__device__ __half g_att1h[(size_t)N2V * DD];
__device__ __half g_att2h[(size_t)N1V * DD];
__device__ __half g_w1h[FPAD * DD];
__device__ __half g_w2h[FPAD * DD];
__device__ float g_rmax[N1V], g_rsum[N1V];
__device__ float g_cmax[N2V], g_csum[N2V];
__device__ float g_rpm[(size_t)N1V * 32], g_rps[(size_t)N1V * 32];
__device__ float g_cpm[(size_t)N2V * 64], g_cps[(size_t)N2V * 64];
__device__ uint16_t g_rmask[(size_t)N1V * 512];    // [row][blk*16 + warp_n*4 + q]
__device__ uint8_t  g_cmask[(size_t)N2V * 1024];   // [col][blk*16 + warp_m*8 + gr]
__device__ float g_sumv1[DD], g_sumv2[DD];
__device__ float g_tpart1[FPAD * 32], g_tpart2[FPAD * 32];

// ======================= asm helpers =======================
static __device__ __forceinline__ uint32_t smem_u32(const void* p) {
    uint32_t a;
    asm("{ .reg .u64 t; cvta.to.shared.u64 t, %1; cvt.u32.u64 %0, t; }" : "=r"(a) : "l"(p));
    return a;
}
static __device__ __forceinline__ uint64_t gaddr(const void* p) {
    uint64_t a;
    asm("cvta.to.global.u64 %0, %1;" : "=l"(a) : "l"(p));
    return a;
}
static __device__ __forceinline__ void cpa16(uint32_t dst, uint64_t src) {
    asm volatile("cp.async.cg.shared.global [%0], [%1], 16;" :: "r"(dst), "l"(src));
}
static __device__ __forceinline__ void ldsm_x4(uint32_t& r0, uint32_t& r1, uint32_t& r2, uint32_t& r3, uint32_t addr) {
    asm volatile("ldmatrix.sync.aligned.m8n8.x4.shared.b16 {%0,%1,%2,%3}, [%4];"
                 : "=r"(r0), "=r"(r1), "=r"(r2), "=r"(r3) : "r"(addr));
}
static __device__ __forceinline__ void mma16816(float* d, const uint32_t* a, uint32_t b0, uint32_t b1) {
    asm volatile("mma.sync.aligned.m16n8k16.row.col.f32.f16.f16.f32 "
                 "{%0,%1,%2,%3}, {%4,%5,%6,%7}, {%8,%9}, {%0,%1,%2,%3};"
                 : "+f"(d[0]), "+f"(d[1]), "+f"(d[2]), "+f"(d[3])
                 : "r"(a[0]), "r"(a[1]), "r"(a[2]), "r"(a[3]), "r"(b0), "r"(b1));
}
static __device__ __forceinline__ void mmaq(float* d, const uint32_t* a, uint32_t b0, uint32_t b1) {
    asm volatile("mma.sync.aligned.m16n8k32.row.col.f32.e4m3.e4m3.f32 "
                 "{%0,%1,%2,%3}, {%4,%5,%6,%7}, {%8,%9}, {%0,%1,%2,%3};"
                 : "+f"(d[0]), "+f"(d[1]), "+f"(d[2]), "+f"(d[3])
                 : "r"(a[0]), "r"(a[1]), "r"(a[2]), "r"(a[3]), "r"(b0), "r"(b1));
}
static __device__ __forceinline__ void msmerge(float& m, float& s, float mo, float so) {
    float mn = fmaxf(m, mo);
    s = s * __expf(m - mn) + so * __expf(mo - mn);
    m = mn;
}

// ======================= fp8 raw GEMM, 128x256 block, K=64 tiles =======================
// raw = A.B^T (e4m3, fp32 accum). Stores fp16 logits; stat partials from ROUNDED values;
// emits block-threshold candidate bitmasks (superset of global selection).
__global__ void __launch_bounds__(256, 1)
hgemm8(const uint8_t* __restrict__ A8, const uint8_t* __restrict__ B8,
       __half* __restrict__ Ch, long ldw, int K, int NT,
       float* __restrict__ rpm, float* __restrict__ rps,
       float* __restrict__ cpm, float* __restrict__ cps,
       uint16_t* __restrict__ rmask, uint8_t* __restrict__ cmask)
{
    extern __shared__ char smem[];
    const uint32_t sbase = smem_u32(smem);
    const int STGSZ = 30720;
    const int tid = threadIdx.x, lane = tid & 31, wid = tid >> 5;
    const int warp_m = wid & 1;
    const int warp_n = wid >> 1;
    const int m0 = blockIdx.y * 128;
    const int n0 = blockIdx.x * 256;

    const int arow = lane & 15, acolB = (lane >> 4) << 4;
    const int brow = (lane & 7) + ((lane & 16) >> 1), bcolB = (lane & 8) << 1;

    const uint64_t gA = gaddr(A8);
    const uint64_t gB = gaddr(B8);

    float acc[4][8][4];
#pragma unroll
    for (int i = 0; i < 4; i++)
#pragma unroll
        for (int j = 0; j < 8; j++)
#pragma unroll
            for (int k = 0; k < 4; k++) acc[i][j][k] = 0.f;

    auto load_stage = [&](int kt, int bufi) {
        const int k0 = kt * 64;
        uint32_t sb = sbase + bufi * STGSZ;
#pragma unroll
        for (int i = 0; i < 2; i++) {
            int idx = tid + i * 256;
            int r = idx >> 2, c = (idx & 3) << 4;
            cpa16(sb + (uint32_t)(r * 80 + c), gA + (uint64_t)(m0 + r) * K + k0 + c);
        }
#pragma unroll
        for (int i = 0; i < 4; i++) {
            int idx = tid + i * 256;
            int r = idx >> 2, c = (idx & 3) << 4;
            cpa16(sb + 10240 + (uint32_t)(r * 80 + c), gB + (uint64_t)(n0 + r) * K + k0 + c);
        }
        asm volatile("cp.async.commit_group;" ::: "memory");
    };

    load_stage(0, 0);
    load_stage(1, 1);
    for (int t = 0; t < NT; t++) {
        if (t + 2 < NT) {
            load_stage(t + 2, (t + 2) % 3);
            asm volatile("cp.async.wait_group 2;" ::: "memory");
        } else if (t + 1 < NT) {
            asm volatile("cp.async.wait_group 1;" ::: "memory");
        } else {
            asm volatile("cp.async.wait_group 0;" ::: "memory");
        }
        __syncthreads();
        uint32_t sa = sbase + (t % 3) * STGSZ;
#pragma unroll
        for (int ks = 0; ks < 2; ks++) {
            uint32_t ah[4][4];
#pragma unroll
            for (int mf = 0; mf < 4; mf++) {
                uint32_t addr = sa + (uint32_t)((warp_m * 64 + mf * 16 + arow) * 80 + ks * 32 + acolB);
                ldsm_x4(ah[mf][0], ah[mf][1], ah[mf][2], ah[mf][3], addr);
            }
            uint32_t bh[4][4];
#pragma unroll
            for (int nf2 = 0; nf2 < 4; nf2++) {
                uint32_t addr = sa + 10240 + (uint32_t)((warp_n * 64 + nf2 * 16 + brow) * 80 + ks * 32 + bcolB);
                ldsm_x4(bh[nf2][0], bh[nf2][1], bh[nf2][2], bh[nf2][3], addr);
            }
#pragma unroll
            for (int mf = 0; mf < 4; mf++)
#pragma unroll
                for (int nf = 0; nf < 8; nf++) {
                    int nf2 = nf >> 1, o = (nf & 1) * 2;
                    mmaq(acc[mf][nf], ah[mf], bh[nf2][o], bh[nf2][o + 1]);
                }
        }
        __syncthreads();
    }

    const int gr = lane >> 2, q = lane & 3;
    // ---- round to fp16, store, replace acc with rounded values ----
#pragma unroll
    for (int mf = 0; mf < 4; mf++)
#pragma unroll
        for (int nf = 0; nf < 8; nf++) {
            int row = m0 + warp_m * 64 + mf * 16 + gr;
            int col = n0 + warp_n * 64 + nf * 8 + q * 2;
            __half2 h01 = __floats2half2_rn(acc[mf][nf][0], acc[mf][nf][1]);
            __half2 h23 = __floats2half2_rn(acc[mf][nf][2], acc[mf][nf][3]);
            *reinterpret_cast<__half2*>(Ch + (size_t)row * ldw + col)       = h01;
            *reinterpret_cast<__half2*>(Ch + (size_t)(row + 8) * ldw + col) = h23;
            float2 f01 = __half22float2(h01);
            float2 f23 = __half22float2(h23);
            acc[mf][nf][0] = f01.x; acc[mf][nf][1] = f01.y;
            acc[mf][nf][2] = f23.x; acc[mf][nf][3] = f23.y;
        }
    float rm[8], rs[8];
#pragma unroll
    for (int mf = 0; mf < 4; mf++) {
        float ma = -1e30f, mb = -1e30f;
#pragma unroll
        for (int nf = 0; nf < 8; nf++) {
            ma = fmaxf(ma, fmaxf(acc[mf][nf][0], acc[mf][nf][1]));
            mb = fmaxf(mb, fmaxf(acc[mf][nf][2], acc[mf][nf][3]));
        }
        float sa = 0.f, sb = 0.f;
#pragma unroll
        for (int nf = 0; nf < 8; nf++) {
            sa += __expf(acc[mf][nf][0] - ma) + __expf(acc[mf][nf][1] - ma);
            sb += __expf(acc[mf][nf][2] - mb) + __expf(acc[mf][nf][3] - mb);
        }
        rm[2 * mf] = ma;  rs[2 * mf] = sa;
        rm[2 * mf + 1] = mb;  rs[2 * mf + 1] = sb;
    }
#pragma unroll
    for (int o = 1; o < 4; o <<= 1)
#pragma unroll
        for (int k = 0; k < 8; k++) {
            float mo = __shfl_xor_sync(0xffffffffu, rm[k], o);
            float so = __shfl_xor_sync(0xffffffffu, rs[k], o);
            msmerge(rm[k], rs[k], mo, so);
        }
    float cm[16], cs[16];
#pragma unroll
    for (int nf = 0; nf < 8; nf++)
#pragma unroll
        for (int b = 0; b < 2; b++) {
            int i = nf * 2 + b;
            float mv = -1e30f;
#pragma unroll
            for (int mf = 0; mf < 4; mf++)
                mv = fmaxf(mv, fmaxf(acc[mf][nf][b], acc[mf][nf][b + 2]));
            float sv = 0.f;
#pragma unroll
            for (int mf = 0; mf < 4; mf++)
                sv += __expf(acc[mf][nf][b] - mv) + __expf(acc[mf][nf][b + 2] - mv);
            cm[i] = mv;  cs[i] = sv;
        }
#pragma unroll
    for (int o = 4; o < 32; o <<= 1)
#pragma unroll
        for (int k = 0; k < 16; k++) {
            float mo = __shfl_xor_sync(0xffffffffu, cm[k], o);
            float so = __shfl_xor_sync(0xffffffffu, cs[k], o);
            msmerge(cm[k], cs[k], mo, so);
        }
    float* rowm  = reinterpret_cast<float*>(smem);
    float* rows_ = rowm + 512;
    float* colm  = rows_ + 512;
    float* cols_ = colm + 512;
    if (q == 0) {
#pragma unroll
        for (int mf = 0; mf < 4; mf++) {
            int lr = warp_m * 64 + mf * 16 + gr;
            rowm [lr * 4 + warp_n] = rm[2 * mf];
            rows_[lr * 4 + warp_n] = rs[2 * mf];
            rowm [(lr + 8) * 4 + warp_n] = rm[2 * mf + 1];
            rows_[(lr + 8) * 4 + warp_n] = rs[2 * mf + 1];
        }
    }
    if (lane < 4) {
#pragma unroll
        for (int nf = 0; nf < 8; nf++)
#pragma unroll
            for (int b = 0; b < 2; b++) {
                int cc = warp_n * 64 + nf * 8 + lane * 2 + b;
                colm [warp_m * 256 + cc] = cm[nf * 2 + b];
                cols_[warp_m * 256 + cc] = cs[nf * 2 + b];
            }
    }
    __syncthreads();
    if (tid < 128) {
        float M = rowm[tid * 4], S = rows_[tid * 4];
#pragma unroll
        for (int w = 1; w < 4; w++) msmerge(M, S, rowm[tid * 4 + w], rows_[tid * 4 + w]);
        rpm[(size_t)(m0 + tid) * 32 + blockIdx.x] = M;
        rps[(size_t)(m0 + tid) * 32 + blockIdx.x] = S;
    }
    {
        float M = colm[tid], S = cols_[tid];
        msmerge(M, S, colm[256 + tid], cols_[256 + tid]);
        cpm[(size_t)(n0 + tid) * 64 + blockIdx.y] = M;
        cps[(size_t)(n0 + tid) * 64 + blockIdx.y] = S;
    }
    // ---- candidate bitmask emission (block thresholds; superset of global) ----
#pragma unroll
    for (int mf = 0; mf < 4; mf++)
#pragma unroll
        for (int h = 0; h < 2; h++) {
            int lr = warp_m * 64 + mf * 16 + gr + h * 8;
            float bm = fmaxf(fmaxf(rowm[lr * 4], rowm[lr * 4 + 1]),
                             fmaxf(rowm[lr * 4 + 2], rowm[lr * 4 + 3]));
            float thr = bm - STHR;
            uint32_t mword = 0;
#pragma unroll
            for (int nf = 0; nf < 8; nf++)
#pragma unroll
                for (int b = 0; b < 2; b++)
                    if (acc[mf][nf][h * 2 + b] > thr) mword |= 1u << (nf * 2 + b);
            rmask[(size_t)(m0 + lr) * 512 + blockIdx.x * 16 + warp_n * 4 + q] = (uint16_t)mword;
        }
#pragma unroll
    for (int nf = 0; nf < 8; nf++)
#pragma unroll
        for (int b = 0; b < 2; b++) {
            int cc = warp_n * 64 + nf * 8 + q * 2 + b;
            float thr = fmaxf(colm[cc], colm[256 + cc]) - STHR;
            uint32_t mword = 0;
#pragma unroll
            for (int mf = 0; mf < 4; mf++)
#pragma unroll
                for (int h = 0; h < 2; h++)
                    if (acc[mf][nf][b + h * 2] > thr) mword |= 1u << (mf * 2 + h);
            cmask[(size_t)(n0 + cc) * 1024 + blockIdx.y * 16 + warp_m * 8 + gr] = (uint8_t)mword;
        }
}

// ======================= fp16 transform GEMM (merged z=2), tanh+rowsum epilogue ======
__global__ void __launch_bounds__(256, 1)
tgemm(const __half* __restrict__ Ah, const __half* __restrict__ Bh,
      const __half* __restrict__ Ah2, const __half* __restrict__ Bh2,
      int K, int NT, int Mvalid,
      const float* __restrict__ bias, float* __restrict__ tpart,
      const float* __restrict__ bias2, float* __restrict__ tpart2)
{
    extern __shared__ char smem[];
    const uint32_t sbase = smem_u32(smem);
    const int STGSZ = 30720;
    const int tid = threadIdx.x, lane = tid & 31, wid = tid >> 5;
    const int warp_m = wid & 1;
    const int warp_n = wid >> 1;
    const int m0 = blockIdx.y * 128;
    const int n0 = blockIdx.x * 256;

    const __half* Aop = blockIdx.z ? Ah2 : Ah;
    const __half* Bop = blockIdx.z ? Bh2 : Bh;

    const int arow = lane & 15, acol = (lane >> 4) << 3;
    const int brow = (lane & 7) + ((lane & 16) >> 1);
    const int bcol = lane & 8;

    const uint64_t gAh = gaddr(Aop);
    const uint64_t gBh = gaddr(Bop);

    float acc[4][8][4];
#pragma unroll
    for (int i = 0; i < 4; i++)
#pragma unroll
        for (int j = 0; j < 8; j++)
#pragma unroll
            for (int k = 0; k < 4; k++) acc[i][j][k] = 0.f;

    auto load_stage = [&](int kt, int bufi) {
        const int k0 = kt * 32;
        uint32_t sb = sbase + bufi * STGSZ;
#pragma unroll
        for (int i = 0; i < 2; i++) {
            int idx = tid + i * 256;
            int r = idx >> 2, c = (idx & 3) << 3;
            cpa16(sb + (uint32_t)(r * 40 + c) * 2, gAh + ((uint64_t)(m0 + r) * K + k0 + c) * 2);
        }
#pragma unroll
        for (int i = 0; i < 4; i++) {
            int idx = tid + i * 256;
            int r = idx >> 2, c = (idx & 3) << 3;
            cpa16(sb + 10240 + (uint32_t)(r * 40 + c) * 2, gBh + ((uint64_t)(n0 + r) * K + k0 + c) * 2);
        }
        asm volatile("cp.async.commit_group;" ::: "memory");
    };

    load_stage(0, 0);
    load_stage(1, 1);
    for (int t = 0; t < NT; t++) {
        if (t + 2 < NT) {
            load_stage(t + 2, (t + 2) % 3);
            asm volatile("cp.async.wait_group 2;" ::: "memory");
        } else if (t + 1 < NT) {
            asm volatile("cp.async.wait_group 1;" ::: "memory");
        } else {
            asm volatile("cp.async.wait_group 0;" ::: "memory");
        }
        __syncthreads();
        uint32_t sa = sbase + (t % 3) * STGSZ;
#pragma unroll
        for (int ks = 0; ks < 2; ks++) {
            uint32_t ah[4][4];
#pragma unroll
            for (int mf = 0; mf < 4; mf++) {
                uint32_t addr = sa + (uint32_t)((warp_m * 64 + mf * 16 + arow) * 40 + ks * 16 + acol) * 2;
                ldsm_x4(ah[mf][0], ah[mf][1], ah[mf][2], ah[mf][3], addr);
            }
            uint32_t bh[4][4];
#pragma unroll
            for (int nf2 = 0; nf2 < 4; nf2++) {
                uint32_t addr = sa + 10240 + (uint32_t)((warp_n * 64 + nf2 * 16 + brow) * 40 + ks * 16 + bcol) * 2;
                ldsm_x4(bh[nf2][0], bh[nf2][1], bh[nf2][2], bh[nf2][3], addr);
            }
#pragma unroll
            for (int mf = 0; mf < 4; mf++)
#pragma unroll
                for (int nf = 0; nf < 8; nf++) {
                    int nf2 = nf >> 1, o = (nf & 1) * 2;
                    mma16816(acc[mf][nf], ah[mf], bh[nf2][o], bh[nf2][o + 1]);
                }
        }
        __syncthreads();
    }

    const int gr = lane >> 2, q = lane & 3;
    const float* bs = blockIdx.z ? bias2 : bias;
    float* tp = blockIdx.z ? tpart2 : tpart;
    float rsum[8];
#pragma unroll
    for (int k = 0; k < 8; k++) rsum[k] = 0.f;
#pragma unroll
    for (int mf = 0; mf < 4; mf++) {
        int row = m0 + warp_m * 64 + mf * 16 + gr;
        float bj0 = (row < Mvalid)     ? bs[row]     : 0.f;
        float bj1 = (row + 8 < Mvalid) ? bs[row + 8] : 0.f;
#pragma unroll
        for (int nf = 0; nf < 8; nf++) {
            rsum[mf * 2]     += tanhf(acc[mf][nf][0] + bj0) + tanhf(acc[mf][nf][1] + bj0);
            rsum[mf * 2 + 1] += tanhf(acc[mf][nf][2] + bj1) + tanhf(acc[mf][nf][3] + bj1);
        }
    }
#pragma unroll
    for (int o = 1; o < 4; o <<= 1)
#pragma unroll
        for (int k = 0; k < 8; k++) rsum[k] += __shfl_xor_sync(0xffffffffu, rsum[k], o);
    __syncthreads();
    float* red = reinterpret_cast<float*>(smem);
    if (q == 0) {
#pragma unroll
        for (int mf = 0; mf < 4; mf++) {
            int lr = warp_m * 64 + mf * 16 + gr;
            red[lr * 4 + warp_n]       = rsum[mf * 2];
            red[(lr + 8) * 4 + warp_n] = rsum[mf * 2 + 1];
        }
    }
    __syncthreads();
    if (tid < 128) {
        float s = red[tid * 4] + red[tid * 4 + 1] + red[tid * 4 + 2] + red[tid * 4 + 3];
        int f = m0 + tid;
        if (f < Mvalid) tp[(size_t)f * gridDim.x + blockIdx.x] = s;
    }
}

// ======================= merge softmax stat partials =======================
__global__ void stats_merge_kernel()
{
    int g = blockIdx.x * 8 + (threadIdx.x >> 5);
    int lane = threadIdx.x & 31;
    if (g < N1V) {
        float m = g_rpm[(size_t)g * 32 + lane];
        float s = g_rps[(size_t)g * 32 + lane];
#pragma unroll
        for (int o = 16; o; o >>= 1) {
            float mo = __shfl_xor_sync(0xffffffffu, m, o);
            float so = __shfl_xor_sync(0xffffffffu, s, o);
            msmerge(m, s, mo, so);
        }
        if (lane == 0) { g_rmax[g] = m; g_rsum[g] = s; }
    } else {
        int c = g - N1V;
        float m = g_cpm[(size_t)c * 64 + lane];
        float s = g_cps[(size_t)c * 64 + lane];
        msmerge(m, s, g_cpm[(size_t)c * 64 + 32 + lane], g_cps[(size_t)c * 64 + 32 + lane]);
#pragma unroll
        for (int o = 16; o; o >>= 1) {
            float mo = __shfl_xor_sync(0xffffffffu, m, o);
            float so = __shfl_xor_sync(0xffffffffu, s, o);
            msmerge(m, s, mo, so);
        }
        if (lane == 0) { g_cmax[c] = m; g_csum[c] = s; }
    }
}

// ======================= refine + gather (mask-driven, fused) =======================
// MODE 0: rows (alpha2). A = m1[row], B = m2, masks = g_rmask, raw read row-major.
// MODE 1: cols (alpha1). A = m2[col], B = m1, masks = g_cmask, raw read col-major.
template<int MODE>
__global__ void refine_gather_kernel(const float* __restrict__ Avec, const float* __restrict__ Bmat,
                                     const void* __restrict__ maskp,
                                     const __half* __restrict__ rawp,
                                     const float* __restrict__ gM, const float* __restrict__ gS,
                                     __half* __restrict__ att)
{
    __shared__ float a[DD];
    __shared__ int   jl[KEEPMAX];
    __shared__ float xap[KEEPMAX], xs[KEEPMAX], wl[KEEPMAX];
    __shared__ float red[8];
    __shared__ int wtot[8];
    __shared__ int nk;
    int row = blockIdx.x;
    int t = threadIdx.x, lane = t & 31, w = t >> 5;
    float gmax = gM[row];
    float thr = gmax - STHR;

#pragma unroll
    for (int k = 0; k < 4; k++) a[t + k * 256] = Avec[(size_t)row * DD + t + k * 256];

    // ---- candidate scan from bitmasks (global-threshold filter via fp16 raw gather) ----
    int cidx[8];
    float cx[8];
    int c = 0;
    if (MODE == 0) {
        const uint16_t* mw = reinterpret_cast<const uint16_t*>(maskp) + (size_t)row * 512;
#pragma unroll
        for (int it = 0; it < 2; it++) {
            int wi = t + it * 256;
            uint32_t m = mw[wi];
            int blk = wi >> 4, sub = wi & 15;
            while (m) {
                int i = __ffs(m) - 1;
                m &= m - 1;
                int col = blk * 256 + (sub >> 2) * 64 + (i >> 1) * 8 + (sub & 3) * 2 + (i & 1);
                float x = __half2float(rawp[(size_t)row * N2V + col]);
                if (x > thr && c < 8) { cidx[c] = col; cx[c] = x; c++; }
            }
        }
    } else {
        const uint8_t* mw = reinterpret_cast<const uint8_t*>(maskp) + (size_t)row * 1024;
#pragma unroll
        for (int it = 0; it < 4; it++) {
            int wi = t + it * 256;
            uint32_t m = mw[wi];
            int blk = wi >> 4, sub = wi & 15;
            while (m) {
                int i = __ffs(m) - 1;
                m &= m - 1;
                int r = blk * 128 + (sub >> 3) * 64 + (i >> 1) * 16 + (sub & 7) + (i & 1) * 8;
                float x = __half2float(rawp[(size_t)r * N2V + row]);
                if (x > thr && c < 8) { cidx[c] = r; cx[c] = x; c++; }
            }
        }
    }
    // ordered compaction
    int v = c;
#pragma unroll
    for (int o = 1; o < 32; o <<= 1) {
        int u = __shfl_up_sync(0xffffffffu, v, o);
        if (lane >= o) v += u;
    }
    if (lane == 31) wtot[w] = v;
    __syncthreads();
    int woff = 0;
#pragma unroll
    for (int s = 0; s < 8; s++) if (s < w) woff += wtot[s];
    int off = woff + v - c;
    for (int k = 0; k < c; k++) {
        if (off + k < KEEPMAX) { jl[off + k] = cidx[k]; xap[off + k] = cx[k]; }
    }
    if (t == 0) {
        int tot = wtot[0] + wtot[1] + wtot[2] + wtot[3] + wtot[4] + wtot[5] + wtot[6] + wtot[7];
        nk = tot < KEEPMAX ? tot : KEEPMAX;
    }
    __syncthreads();

    int n = nk;
    for (int s = 0; s < n; s++) {
        const float* b = Bmat + (size_t)jl[s] * DD;
        float p = 0.f;
#pragma unroll
        for (int k = 0; k < 4; k++) p += a[t + k * 256] * b[t + k * 256];
#pragma unroll
        for (int o = 16; o; o >>= 1) p += __shfl_xor_sync(0xffffffffu, p, o);
        if (lane == 0) red[w] = p;
        __syncthreads();
        if (t == 0) xs[s] = red[0] + red[1] + red[2] + red[3] + red[4] + red[5] + red[6] + red[7];
        __syncthreads();
    }
    if (t == 0) {
        float Mapp = gmax, Sapp = gS[row];
        float Mn = Mapp;
        for (int s = 0; s < n; s++) Mn = fmaxf(Mn, xs[s]);
        float S = Sapp * __expf(Mapp - Mn);
        for (int s = 0; s < n; s++)
            S += __expf(xs[s] - Mn) - __expf(xap[s] - Mn);
        float inv = 1.0f / S;
        for (int s = 0; s < n; s++) wl[s] = __expf(xs[s] - Mn) * inv;
    }
    __syncthreads();

    float a0 = 0.f, a1 = 0.f, a2 = 0.f, a3 = 0.f;
    for (int s = 0; s < n; s++) {
        int j = jl[s];
        float wv = wl[s];
        float4 vv = *reinterpret_cast<const float4*>(Bmat + (size_t)j * DD + t * 4);
        a0 += wv * vv.x; a1 += wv * vv.y; a2 += wv * vv.z; a3 += wv * vv.w;
    }
    __half2* d = reinterpret_cast<__half2*>(att + (size_t)row * DD + t * 4);
    d[0] = __floats2half2_rn(a0, a1);
    d[1] = __floats2half2_rn(a2, a3);
}

// ======================= column sums of fp16 att -> sumv =======================
__global__ void colsum_kernel(const __half* __restrict__ att, float* __restrict__ sumv)
{
    int lane = threadIdx.x & 31, w = threadIdx.x >> 5;
    int col = blockIdx.x * 32 + lane;
    float s = 0.f;
#pragma unroll 8
    for (int r = 0; r < 1024; r++)
        s += __half2float(att[(size_t)(w * 1024 + r) * DD + col]);
    __shared__ float sh[8][33];
    sh[w][lane] = s;
    __syncthreads();
    if (threadIdx.x < 32) {
        float t = 0.f;
#pragma unroll
        for (int q = 0; q < 8; q++) t += sh[q][threadIdx.x];
        sumv[blockIdx.x * 32 + threadIdx.x] = t;
    }
}

// ======================= combined prep casts =======================
#define M1N (N1V * DD)
#define M2N (N2V * DD)
#define WN  (FPAD * DD)
__global__ void prep_kernel(const float* __restrict__ m1, const float* __restrict__ m2,
                            const float* __restrict__ W1, const float* __restrict__ W2,
                            uint8_t* __restrict__ m1q, uint8_t* __restrict__ m2q,
                            __half* __restrict__ w1h, __half* __restrict__ w2h)
{
    int i = blockIdx.x * 256 + threadIdx.x;
    if (i < M1N) {
        __nv_fp8_e4m3 v(m1[i]);
        m1q[i] = *reinterpret_cast<uint8_t*>(&v);
    } else if (i < M1N + M2N) {
        int k = i - M1N;
        __nv_fp8_e4m3 v(m2[k]);
        m2q[k] = *reinterpret_cast<uint8_t*>(&v);
    } else if (i < M1N + M2N + WN) {
        int k = i - M1N - M2N;
        int r = k / DD;
        w1h[k] = __float2half_rn(r < FF ? W1[k] : 0.f);
    } else if (i < M1N + M2N + 2 * WN) {
        int k = i - M1N - M2N - WN;
        int r = k / DD;
        w2h[k] = __float2half_rn(r < FF ? W2[k] : 0.f);
    }
}

// ======================= finalize =======================
__global__ void finalize_kernel(const float* __restrict__ Wf1, const float* __restrict__ bf1,
                                const float* __restrict__ Wf2, const float* __restrict__ bf2,
                                float* __restrict__ out)
{
    int g = blockIdx.x * 8 + (threadIdx.x >> 5);
    int lane = threadIdx.x & 31;
    const float inv = 1.0f / 8192.0f;
    if (g < FF) {
        const float* w = Wf1 + (size_t)g * DD;
        float d = 0.f;
        for (int l = lane; l < DD; l += 32) d += w[l] * g_sumv2[l];
#pragma unroll
        for (int o = 16; o; o >>= 1) d += __shfl_xor_sync(0xffffffffu, d, o);
        if (lane == 0) {
            float filt = 1.0f / (1.0f + __expf(-(d * inv + bf1[g])));
            float t = 0.f;
#pragma unroll
            for (int b = 0; b < 32; b++) t += g_tpart1[g * 32 + b];
            out[g] = t * inv * filt;
        }
    } else if (g < 2 * FF) {
        int f = g - FF;
        const float* w = Wf2 + (size_t)f * DD;
        float d = 0.f;
        for (int l = lane; l < DD; l += 32) d += w[l] * g_sumv1[l];
#pragma unroll
        for (int o = 16; o; o >>= 1) d += __shfl_xor_sync(0xffffffffu, d, o);
        if (lane == 0) {
            float filt = 1.0f / (1.0f + __expf(-(d * inv + bf2[f])));
            float t = 0.f;
#pragma unroll
            for (int b = 0; b < 32; b++) t += g_tpart2[f * 32 + b];
            out[FF + f] = t * inv * filt;
        }
    }
}

// ======================= launch =======================
extern "C" void kernel_launch(void* const* d_in, const int* in_sizes, int n_in,
                              void* d_out, int out_size)
{
    const float* m1  = (const float*)d_in[0];
    const float* m2  = (const float*)d_in[1];
    const float* Wf1 = (const float*)d_in[2];
    const float* bf1 = (const float*)d_in[3];
    const float* Wf2 = (const float*)d_in[4];
    const float* bf2 = (const float*)d_in[5];
    const float* W1  = (const float*)d_in[6];
    const float* b1  = (const float*)d_in[7];
    const float* W2  = (const float*)d_in[8];
    const float* b2  = (const float*)d_in[9];
    float* out = (float*)d_out;

    float *tpart1, *tpart2, *rpm, *rps, *cpm, *cps, *sumv1, *sumv2;
    float *rmaxp, *rsump, *cmaxp, *csump;
    uint8_t *m1q, *m2q, *cmask;
    uint16_t *rmask;
    __half *rawh, *att1h, *att2h, *w1h, *w2h;
    cudaGetSymbolAddress((void**)&rawh,  g_rawh);
    cudaGetSymbolAddress((void**)&m1q,   g_m1q);
    cudaGetSymbolAddress((void**)&m2q,   g_m2q);
    cudaGetSymbolAddress((void**)&att1h, g_att1h);
    cudaGetSymbolAddress((void**)&att2h, g_att2h);
    cudaGetSymbolAddress((void**)&w1h,   g_w1h);
    cudaGetSymbolAddress((void**)&w2h,   g_w2h);
    cudaGetSymbolAddress((void**)&tpart1, g_tpart1);
    cudaGetSymbolAddress((void**)&tpart2, g_tpart2);
    cudaGetSymbolAddress((void**)&rpm, g_rpm);
    cudaGetSymbolAddress((void**)&rps, g_rps);
    cudaGetSymbolAddress((void**)&cpm, g_cpm);
    cudaGetSymbolAddress((void**)&cps, g_cps);
    cudaGetSymbolAddress((void**)&rmask, g_rmask);
    cudaGetSymbolAddress((void**)&cmask, g_cmask);
    cudaGetSymbolAddress((void**)&sumv1, g_sumv1);
    cudaGetSymbolAddress((void**)&sumv2, g_sumv2);
    cudaGetSymbolAddress((void**)&rmaxp, g_rmax);
    cudaGetSymbolAddress((void**)&rsump, g_rsum);
    cudaGetSymbolAddress((void**)&cmaxp, g_cmax);
    cudaGetSymbolAddress((void**)&csump, g_csum);

    cudaFuncSetAttribute(hgemm8, cudaFuncAttributeMaxDynamicSharedMemorySize, 92160);
    cudaFuncSetAttribute(tgemm,  cudaFuncAttributeMaxDynamicSharedMemorySize, 92160);

    // 0) combined prep casts (m1/m2 -> e4m3, W1/W2 -> fp16 padded)
    prep_kernel<<<(M1N + M2N + 2 * WN + 255) / 256, 256>>>(
        m1, m2, W1, W2, m1q, m2q, w1h, w2h);

    // 1) approx raw = m1 @ m2^T, e4m3 MMA; fp16 store + fused stats + candidate bitmasks
    hgemm8<<<dim3(N2V / 256, N1V / 128), 256, 92160>>>(
        m1q, m2q, rawh, N2V, DD, DD / 64, rpm, rps, cpm, cps, rmask, cmask);

    // 2) merge approx stats (M, S)
    stats_merge_kernel<<<(N1V + N2V) / 8, 256>>>();

    // 3) refine + gather (mask scan -> global-threshold filter -> exact fp32 logits
    //    -> exact softmax -> fp32 gather -> fp16 att)
    refine_gather_kernel<0><<<N1V, 256>>>(m1, m2, rmask, rawh, rmaxp, rsump, att2h);
    refine_gather_kernel<1><<<N2V, 256>>>(m2, m1, cmask, rawh, cmaxp, csump, att1h);

    // 4) column sums for the filter path
    colsum_kernel<<<DD / 32, 256>>>(att1h, sumv1);
    colsum_kernel<<<DD / 32, 256>>>(att2h, sumv2);

    // 5) transform GEMMs merged (z selects W1/att1 vs W2/att2), fused tanh+rowsum
    tgemm<<<dim3(N2V / 256, FPAD / 128, 2), 256, 92160>>>(
        w1h, att1h, w2h, att2h, DD, DD / 32, FF, b1, tpart1, b2, tpart2);

    // 6) filters + outputs
    finalize_kernel<<<200, 256>>>(Wf1, bf1, Wf2, bf2, out);
}

// round 17
// speedup vs baseline: 1.7792x; 1.0425x over previous
#include <cuda_runtime.h>
#include <cuda_fp16.h>
#include <cuda_fp8.h>
#include <math.h>
#include <stdint.h>
#include <stddef.h>

#define N1V 8192
#define N2V 8192
#define DD  1024
#define FF  800
#define FPAD 896
#define KEEPMAX 64
#define STHR 20.0f

// ======================= scratch (device globals) =======================
__device__ __half  g_rawh[(size_t)N1V * N2V];    // approx logits fp16
__device__ uint8_t g_m1q[(size_t)N1V * DD];
__device__ uint8_t g_m2q[(size_t)N2V * DD];
__device__ __half g_att1h[(size_t)N2V * DD];
__device__ __half g_att2h[(size_t)N1V * DD];
__device__ __half g_w1h[FPAD * DD];
__device__ __half g_w2h[FPAD * DD];
__device__ float g_rmax[N1V], g_rsum[N1V];
__device__ float g_cmax[N2V], g_csum[N2V];
__device__ float g_rpm[(size_t)N1V * 32], g_rps[(size_t)N1V * 32];
__device__ float g_cpm[(size_t)N2V * 64], g_cps[(size_t)N2V * 64];
__device__ uint16_t g_rmask[(size_t)N1V * 512];    // [row][blk*16 + warp_n*4 + q]
__device__ uint8_t  g_cmask[(size_t)N2V * 1024];   // [col][blk*16 + warp_m*8 + gr]
__device__ float g_sumv1[DD], g_sumv2[DD];
__device__ float g_tpart1[FPAD * 32], g_tpart2[FPAD * 32];

// ======================= asm helpers =======================
static __device__ __forceinline__ uint32_t smem_u32(const void* p) {
    uint32_t a;
    asm("{ .reg .u64 t; cvta.to.shared.u64 t, %1; cvt.u32.u64 %0, t; }" : "=r"(a) : "l"(p));
    return a;
}
static __device__ __forceinline__ uint64_t gaddr(const void* p) {
    uint64_t a;
    asm("cvta.to.global.u64 %0, %1;" : "=l"(a) : "l"(p));
    return a;
}
static __device__ __forceinline__ void cpa16(uint32_t dst, uint64_t src) {
    asm volatile("cp.async.cg.shared.global [%0], [%1], 16;" :: "r"(dst), "l"(src));
}
static __device__ __forceinline__ void ldsm_x4(uint32_t& r0, uint32_t& r1, uint32_t& r2, uint32_t& r3, uint32_t addr) {
    asm volatile("ldmatrix.sync.aligned.m8n8.x4.shared.b16 {%0,%1,%2,%3}, [%4];"
                 : "=r"(r0), "=r"(r1), "=r"(r2), "=r"(r3) : "r"(addr));
}
static __device__ __forceinline__ void mma16816(float* d, const uint32_t* a, uint32_t b0, uint32_t b1) {
    asm volatile("mma.sync.aligned.m16n8k16.row.col.f32.f16.f16.f32 "
                 "{%0,%1,%2,%3}, {%4,%5,%6,%7}, {%8,%9}, {%0,%1,%2,%3};"
                 : "+f"(d[0]), "+f"(d[1]), "+f"(d[2]), "+f"(d[3])
                 : "r"(a[0]), "r"(a[1]), "r"(a[2]), "r"(a[3]), "r"(b0), "r"(b1));
}
static __device__ __forceinline__ void mmaq(float* d, const uint32_t* a, uint32_t b0, uint32_t b1) {
    asm volatile("mma.sync.aligned.m16n8k32.row.col.f32.e4m3.e4m3.f32 "
                 "{%0,%1,%2,%3}, {%4,%5,%6,%7}, {%8,%9}, {%0,%1,%2,%3};"
                 : "+f"(d[0]), "+f"(d[1]), "+f"(d[2]), "+f"(d[3])
                 : "r"(a[0]), "r"(a[1]), "r"(a[2]), "r"(a[3]), "r"(b0), "r"(b1));
}
static __device__ __forceinline__ void msmerge(float& m, float& s, float mo, float so) {
    float mn = fmaxf(m, mo);
    s = s * __expf(m - mn) + so * __expf(mo - mn);
    m = mn;
}

// ======================= fp8 raw GEMM, 128x256 block, K=64 tiles =======================
__global__ void __launch_bounds__(256, 1)
hgemm8(const uint8_t* __restrict__ A8, const uint8_t* __restrict__ B8,
       __half* __restrict__ Ch, long ldw, int K, int NT,
       float* __restrict__ rpm, float* __restrict__ rps,
       float* __restrict__ cpm, float* __restrict__ cps,
       uint16_t* __restrict__ rmask, uint8_t* __restrict__ cmask)
{
    extern __shared__ char smem[];
    const uint32_t sbase = smem_u32(smem);
    const int STGSZ = 30720;
    const int tid = threadIdx.x, lane = tid & 31, wid = tid >> 5;
    const int warp_m = wid & 1;
    const int warp_n = wid >> 1;
    const int m0 = blockIdx.y * 128;
    const int n0 = blockIdx.x * 256;

    const int arow = lane & 15, acolB = (lane >> 4) << 4;
    const int brow = (lane & 7) + ((lane & 16) >> 1), bcolB = (lane & 8) << 1;

    const uint64_t gA = gaddr(A8);
    const uint64_t gB = gaddr(B8);

    float acc[4][8][4];
#pragma unroll
    for (int i = 0; i < 4; i++)
#pragma unroll
        for (int j = 0; j < 8; j++)
#pragma unroll
            for (int k = 0; k < 4; k++) acc[i][j][k] = 0.f;

    auto load_stage = [&](int kt, int bufi) {
        const int k0 = kt * 64;
        uint32_t sb = sbase + bufi * STGSZ;
#pragma unroll
        for (int i = 0; i < 2; i++) {
            int idx = tid + i * 256;
            int r = idx >> 2, c = (idx & 3) << 4;
            cpa16(sb + (uint32_t)(r * 80 + c), gA + (uint64_t)(m0 + r) * K + k0 + c);
        }
#pragma unroll
        for (int i = 0; i < 4; i++) {
            int idx = tid + i * 256;
            int r = idx >> 2, c = (idx & 3) << 4;
            cpa16(sb + 10240 + (uint32_t)(r * 80 + c), gB + (uint64_t)(n0 + r) * K + k0 + c);
        }
        asm volatile("cp.async.commit_group;" ::: "memory");
    };

    load_stage(0, 0);
    load_stage(1, 1);
    for (int t = 0; t < NT; t++) {
        if (t + 2 < NT) {
            load_stage(t + 2, (t + 2) % 3);
            asm volatile("cp.async.wait_group 2;" ::: "memory");
        } else if (t + 1 < NT) {
            asm volatile("cp.async.wait_group 1;" ::: "memory");
        } else {
            asm volatile("cp.async.wait_group 0;" ::: "memory");
        }
        __syncthreads();
        uint32_t sa = sbase + (t % 3) * STGSZ;
#pragma unroll
        for (int ks = 0; ks < 2; ks++) {
            uint32_t ah[4][4];
#pragma unroll
            for (int mf = 0; mf < 4; mf++) {
                uint32_t addr = sa + (uint32_t)((warp_m * 64 + mf * 16 + arow) * 80 + ks * 32 + acolB);
                ldsm_x4(ah[mf][0], ah[mf][1], ah[mf][2], ah[mf][3], addr);
            }
            uint32_t bh[4][4];
#pragma unroll
            for (int nf2 = 0; nf2 < 4; nf2++) {
                uint32_t addr = sa + 10240 + (uint32_t)((warp_n * 64 + nf2 * 16 + brow) * 80 + ks * 32 + bcolB);
                ldsm_x4(bh[nf2][0], bh[nf2][1], bh[nf2][2], bh[nf2][3], addr);
            }
#pragma unroll
            for (int mf = 0; mf < 4; mf++)
#pragma unroll
                for (int nf = 0; nf < 8; nf++) {
                    int nf2 = nf >> 1, o = (nf & 1) * 2;
                    mmaq(acc[mf][nf], ah[mf], bh[nf2][o], bh[nf2][o + 1]);
                }
        }
        __syncthreads();
    }

    const int gr = lane >> 2, q = lane & 3;
#pragma unroll
    for (int mf = 0; mf < 4; mf++)
#pragma unroll
        for (int nf = 0; nf < 8; nf++) {
            int row = m0 + warp_m * 64 + mf * 16 + gr;
            int col = n0 + warp_n * 64 + nf * 8 + q * 2;
            __half2 h01 = __floats2half2_rn(acc[mf][nf][0], acc[mf][nf][1]);
            __half2 h23 = __floats2half2_rn(acc[mf][nf][2], acc[mf][nf][3]);
            *reinterpret_cast<__half2*>(Ch + (size_t)row * ldw + col)       = h01;
            *reinterpret_cast<__half2*>(Ch + (size_t)(row + 8) * ldw + col) = h23;
            float2 f01 = __half22float2(h01);
            float2 f23 = __half22float2(h23);
            acc[mf][nf][0] = f01.x; acc[mf][nf][1] = f01.y;
            acc[mf][nf][2] = f23.x; acc[mf][nf][3] = f23.y;
        }
    float rm[8], rs[8];
#pragma unroll
    for (int mf = 0; mf < 4; mf++) {
        float ma = -1e30f, mb = -1e30f;
#pragma unroll
        for (int nf = 0; nf < 8; nf++) {
            ma = fmaxf(ma, fmaxf(acc[mf][nf][0], acc[mf][nf][1]));
            mb = fmaxf(mb, fmaxf(acc[mf][nf][2], acc[mf][nf][3]));
        }
        float sa = 0.f, sb = 0.f;
#pragma unroll
        for (int nf = 0; nf < 8; nf++) {
            sa += __expf(acc[mf][nf][0] - ma) + __expf(acc[mf][nf][1] - ma);
            sb += __expf(acc[mf][nf][2] - mb) + __expf(acc[mf][nf][3] - mb);
        }
        rm[2 * mf] = ma;  rs[2 * mf] = sa;
        rm[2 * mf + 1] = mb;  rs[2 * mf + 1] = sb;
    }
#pragma unroll
    for (int o = 1; o < 4; o <<= 1)
#pragma unroll
        for (int k = 0; k < 8; k++) {
            float mo = __shfl_xor_sync(0xffffffffu, rm[k], o);
            float so = __shfl_xor_sync(0xffffffffu, rs[k], o);
            msmerge(rm[k], rs[k], mo, so);
        }
    float cm[16], cs[16];
#pragma unroll
    for (int nf = 0; nf < 8; nf++)
#pragma unroll
        for (int b = 0; b < 2; b++) {
            int i = nf * 2 + b;
            float mv = -1e30f;
#pragma unroll
            for (int mf = 0; mf < 4; mf++)
                mv = fmaxf(mv, fmaxf(acc[mf][nf][b], acc[mf][nf][b + 2]));
            float sv = 0.f;
#pragma unroll
            for (int mf = 0; mf < 4; mf++)
                sv += __expf(acc[mf][nf][b] - mv) + __expf(acc[mf][nf][b + 2] - mv);
            cm[i] = mv;  cs[i] = sv;
        }
#pragma unroll
    for (int o = 4; o < 32; o <<= 1)
#pragma unroll
        for (int k = 0; k < 16; k++) {
            float mo = __shfl_xor_sync(0xffffffffu, cm[k], o);
            float so = __shfl_xor_sync(0xffffffffu, cs[k], o);
            msmerge(cm[k], cs[k], mo, so);
        }
    float* rowm  = reinterpret_cast<float*>(smem);
    float* rows_ = rowm + 512;
    float* colm  = rows_ + 512;
    float* cols_ = colm + 512;
    if (q == 0) {
#pragma unroll
        for (int mf = 0; mf < 4; mf++) {
            int lr = warp_m * 64 + mf * 16 + gr;
            rowm [lr * 4 + warp_n] = rm[2 * mf];
            rows_[lr * 4 + warp_n] = rs[2 * mf];
            rowm [(lr + 8) * 4 + warp_n] = rm[2 * mf + 1];
            rows_[(lr + 8) * 4 + warp_n] = rs[2 * mf + 1];
        }
    }
    if (lane < 4) {
#pragma unroll
        for (int nf = 0; nf < 8; nf++)
#pragma unroll
            for (int b = 0; b < 2; b++) {
                int cc = warp_n * 64 + nf * 8 + lane * 2 + b;
                colm [warp_m * 256 + cc] = cm[nf * 2 + b];
                cols_[warp_m * 256 + cc] = cs[nf * 2 + b];
            }
    }
    __syncthreads();
    if (tid < 128) {
        float M = rowm[tid * 4], S = rows_[tid * 4];
#pragma unroll
        for (int w = 1; w < 4; w++) msmerge(M, S, rowm[tid * 4 + w], rows_[tid * 4 + w]);
        rpm[(size_t)(m0 + tid) * 32 + blockIdx.x] = M;
        rps[(size_t)(m0 + tid) * 32 + blockIdx.x] = S;
    }
    {
        float M = colm[tid], S = cols_[tid];
        msmerge(M, S, colm[256 + tid], cols_[256 + tid]);
        cpm[(size_t)(n0 + tid) * 64 + blockIdx.y] = M;
        cps[(size_t)(n0 + tid) * 64 + blockIdx.y] = S;
    }
    // ---- candidate bitmask emission ----
#pragma unroll
    for (int mf = 0; mf < 4; mf++)
#pragma unroll
        for (int h = 0; h < 2; h++) {
            int lr = warp_m * 64 + mf * 16 + gr + h * 8;
            float bm = fmaxf(fmaxf(rowm[lr * 4], rowm[lr * 4 + 1]),
                             fmaxf(rowm[lr * 4 + 2], rowm[lr * 4 + 3]));
            float thr = bm - STHR;
            uint32_t mword = 0;
#pragma unroll
            for (int nf = 0; nf < 8; nf++)
#pragma unroll
                for (int b = 0; b < 2; b++)
                    if (acc[mf][nf][h * 2 + b] > thr) mword |= 1u << (nf * 2 + b);
            rmask[(size_t)(m0 + lr) * 512 + blockIdx.x * 16 + warp_n * 4 + q] = (uint16_t)mword;
        }
#pragma unroll
    for (int nf = 0; nf < 8; nf++)
#pragma unroll
        for (int b = 0; b < 2; b++) {
            int cc = warp_n * 64 + nf * 8 + q * 2 + b;
            float thr = fmaxf(colm[cc], colm[256 + cc]) - STHR;
            uint32_t mword = 0;
#pragma unroll
            for (int mf = 0; mf < 4; mf++)
#pragma unroll
                for (int h = 0; h < 2; h++)
                    if (acc[mf][nf][b + h * 2] > thr) mword |= 1u << (mf * 2 + h);
            cmask[(size_t)(n0 + cc) * 1024 + blockIdx.y * 16 + warp_m * 8 + gr] = (uint8_t)mword;
        }
}

// ======================= fp16 transform GEMM (merged z=2), tanh+rowsum epilogue ======
__global__ void __launch_bounds__(256, 1)
tgemm(const __half* __restrict__ Ah, const __half* __restrict__ Bh,
      const __half* __restrict__ Ah2, const __half* __restrict__ Bh2,
      int K, int NT, int Mvalid,
      const float* __restrict__ bias, float* __restrict__ tpart,
      const float* __restrict__ bias2, float* __restrict__ tpart2)
{
    extern __shared__ char smem[];
    const uint32_t sbase = smem_u32(smem);
    const int STGSZ = 30720;
    const int tid = threadIdx.x, lane = tid & 31, wid = tid >> 5;
    const int warp_m = wid & 1;
    const int warp_n = wid >> 1;
    const int m0 = blockIdx.y * 128;
    const int n0 = blockIdx.x * 256;

    const __half* Aop = blockIdx.z ? Ah2 : Ah;
    const __half* Bop = blockIdx.z ? Bh2 : Bh;

    const int arow = lane & 15, acol = (lane >> 4) << 3;
    const int brow = (lane & 7) + ((lane & 16) >> 1);
    const int bcol = lane & 8;

    const uint64_t gAh = gaddr(Aop);
    const uint64_t gBh = gaddr(Bop);

    float acc[4][8][4];
#pragma unroll
    for (int i = 0; i < 4; i++)
#pragma unroll
        for (int j = 0; j < 8; j++)
#pragma unroll
            for (int k = 0; k < 4; k++) acc[i][j][k] = 0.f;

    auto load_stage = [&](int kt, int bufi) {
        const int k0 = kt * 32;
        uint32_t sb = sbase + bufi * STGSZ;
#pragma unroll
        for (int i = 0; i < 2; i++) {
            int idx = tid + i * 256;
            int r = idx >> 2, c = (idx & 3) << 3;
            cpa16(sb + (uint32_t)(r * 40 + c) * 2, gAh + ((uint64_t)(m0 + r) * K + k0 + c) * 2);
        }
#pragma unroll
        for (int i = 0; i < 4; i++) {
            int idx = tid + i * 256;
            int r = idx >> 2, c = (idx & 3) << 3;
            cpa16(sb + 10240 + (uint32_t)(r * 40 + c) * 2, gBh + ((uint64_t)(n0 + r) * K + k0 + c) * 2);
        }
        asm volatile("cp.async.commit_group;" ::: "memory");
    };

    load_stage(0, 0);
    load_stage(1, 1);
    for (int t = 0; t < NT; t++) {
        if (t + 2 < NT) {
            load_stage(t + 2, (t + 2) % 3);
            asm volatile("cp.async.wait_group 2;" ::: "memory");
        } else if (t + 1 < NT) {
            asm volatile("cp.async.wait_group 1;" ::: "memory");
        } else {
            asm volatile("cp.async.wait_group 0;" ::: "memory");
        }
        __syncthreads();
        uint32_t sa = sbase + (t % 3) * STGSZ;
#pragma unroll
        for (int ks = 0; ks < 2; ks++) {
            uint32_t ah[4][4];
#pragma unroll
            for (int mf = 0; mf < 4; mf++) {
                uint32_t addr = sa + (uint32_t)((warp_m * 64 + mf * 16 + arow) * 40 + ks * 16 + acol) * 2;
                ldsm_x4(ah[mf][0], ah[mf][1], ah[mf][2], ah[mf][3], addr);
            }
            uint32_t bh[4][4];
#pragma unroll
            for (int nf2 = 0; nf2 < 4; nf2++) {
                uint32_t addr = sa + 10240 + (uint32_t)((warp_n * 64 + nf2 * 16 + brow) * 40 + ks * 16 + bcol) * 2;
                ldsm_x4(bh[nf2][0], bh[nf2][1], bh[nf2][2], bh[nf2][3], addr);
            }
#pragma unroll
            for (int mf = 0; mf < 4; mf++)
#pragma unroll
                for (int nf = 0; nf < 8; nf++) {
                    int nf2 = nf >> 1, o = (nf & 1) * 2;
                    mma16816(acc[mf][nf], ah[mf], bh[nf2][o], bh[nf2][o + 1]);
                }
        }
        __syncthreads();
    }

    const int gr = lane >> 2, q = lane & 3;
    const float* bs = blockIdx.z ? bias2 : bias;
    float* tp = blockIdx.z ? tpart2 : tpart;
    float rsum[8];
#pragma unroll
    for (int k = 0; k < 8; k++) rsum[k] = 0.f;
#pragma unroll
    for (int mf = 0; mf < 4; mf++) {
        int row = m0 + warp_m * 64 + mf * 16 + gr;
        float bj0 = (row < Mvalid)     ? bs[row]     : 0.f;
        float bj1 = (row + 8 < Mvalid) ? bs[row + 8] : 0.f;
#pragma unroll
        for (int nf = 0; nf < 8; nf++) {
            rsum[mf * 2]     += tanhf(acc[mf][nf][0] + bj0) + tanhf(acc[mf][nf][1] + bj0);
            rsum[mf * 2 + 1] += tanhf(acc[mf][nf][2] + bj1) + tanhf(acc[mf][nf][3] + bj1);
        }
    }
#pragma unroll
    for (int o = 1; o < 4; o <<= 1)
#pragma unroll
        for (int k = 0; k < 8; k++) rsum[k] += __shfl_xor_sync(0xffffffffu, rsum[k], o);
    __syncthreads();
    float* red = reinterpret_cast<float*>(smem);
    if (q == 0) {
#pragma unroll
        for (int mf = 0; mf < 4; mf++) {
            int lr = warp_m * 64 + mf * 16 + gr;
            red[lr * 4 + warp_n]       = rsum[mf * 2];
            red[(lr + 8) * 4 + warp_n] = rsum[mf * 2 + 1];
        }
    }
    __syncthreads();
    if (tid < 128) {
        float s = red[tid * 4] + red[tid * 4 + 1] + red[tid * 4 + 2] + red[tid * 4 + 3];
        int f = m0 + tid;
        if (f < Mvalid) tp[(size_t)f * gridDim.x + blockIdx.x] = s;
    }
}

// ======================= merge softmax stat partials =======================
__global__ void stats_merge_kernel()
{
    int g = blockIdx.x * 8 + (threadIdx.x >> 5);
    int lane = threadIdx.x & 31;
    if (g < N1V) {
        float m = g_rpm[(size_t)g * 32 + lane];
        float s = g_rps[(size_t)g * 32 + lane];
#pragma unroll
        for (int o = 16; o; o >>= 1) {
            float mo = __shfl_xor_sync(0xffffffffu, m, o);
            float so = __shfl_xor_sync(0xffffffffu, s, o);
            msmerge(m, s, mo, so);
        }
        if (lane == 0) { g_rmax[g] = m; g_rsum[g] = s; }
    } else {
        int c = g - N1V;
        float m = g_cpm[(size_t)c * 64 + lane];
        float s = g_cps[(size_t)c * 64 + lane];
        msmerge(m, s, g_cpm[(size_t)c * 64 + 32 + lane], g_cps[(size_t)c * 64 + 32 + lane]);
#pragma unroll
        for (int o = 16; o; o >>= 1) {
            float mo = __shfl_xor_sync(0xffffffffu, m, o);
            float so = __shfl_xor_sync(0xffffffffu, s, o);
            msmerge(m, s, mo, so);
        }
        if (lane == 0) { g_cmax[c] = m; g_csum[c] = s; }
    }
}

// ======================= refine + gather (mask-driven, warp-parallel dots) ============
template<int MODE>
__global__ void refine_gather_kernel(const float* __restrict__ Avec, const float* __restrict__ Bmat,
                                     const void* __restrict__ maskp,
                                     const __half* __restrict__ rawp,
                                     const float* __restrict__ gM, const float* __restrict__ gS,
                                     __half* __restrict__ att)
{
    __shared__ float a[DD];
    __shared__ int   jl[KEEPMAX];
    __shared__ float xap[KEEPMAX], xs[KEEPMAX], wl[KEEPMAX];
    __shared__ int wtot[8];
    __shared__ int nk;
    int row = blockIdx.x;
    int t = threadIdx.x, lane = t & 31, w = t >> 5;
    float gmax = gM[row];
    float thr = gmax - STHR;

#pragma unroll
    for (int k = 0; k < 4; k++) a[t + k * 256] = Avec[(size_t)row * DD + t + k * 256];

    // ---- candidate scan from bitmasks (global-threshold filter via fp16 raw gather) ----
    int cidx[8];
    float cx[8];
    int c = 0;
    if (MODE == 0) {
        const uint16_t* mw = reinterpret_cast<const uint16_t*>(maskp) + (size_t)row * 512;
#pragma unroll
        for (int it = 0; it < 2; it++) {
            int wi = t + it * 256;
            uint32_t m = mw[wi];
            int blk = wi >> 4, sub = wi & 15;
            while (m) {
                int i = __ffs(m) - 1;
                m &= m - 1;
                int col = blk * 256 + (sub >> 2) * 64 + (i >> 1) * 8 + (sub & 3) * 2 + (i & 1);
                float x = __half2float(rawp[(size_t)row * N2V + col]);
                if (x > thr && c < 8) { cidx[c] = col; cx[c] = x; c++; }
            }
        }
    } else {
        const uint8_t* mw = reinterpret_cast<const uint8_t*>(maskp) + (size_t)row * 1024;
#pragma unroll
        for (int it = 0; it < 4; it++) {
            int wi = t + it * 256;
            uint32_t m = mw[wi];
            int blk = wi >> 4, sub = wi & 15;
            while (m) {
                int i = __ffs(m) - 1;
                m &= m - 1;
                int r = blk * 128 + (sub >> 3) * 64 + (i >> 1) * 16 + (sub & 7) + (i & 1) * 8;
                float x = __half2float(rawp[(size_t)r * N2V + row]);
                if (x > thr && c < 8) { cidx[c] = r; cx[c] = x; c++; }
            }
        }
    }
    // ordered compaction
    int v = c;
#pragma unroll
    for (int o = 1; o < 32; o <<= 1) {
        int u = __shfl_up_sync(0xffffffffu, v, o);
        if (lane >= o) v += u;
    }
    if (lane == 31) wtot[w] = v;
    __syncthreads();
    int woff = 0;
#pragma unroll
    for (int s = 0; s < 8; s++) if (s < w) woff += wtot[s];
    int off = woff + v - c;
    for (int k = 0; k < c; k++) {
        if (off + k < KEEPMAX) { jl[off + k] = cidx[k]; xap[off + k] = cx[k]; }
    }
    if (t == 0) {
        int tot = wtot[0] + wtot[1] + wtot[2] + wtot[3] + wtot[4] + wtot[5] + wtot[6] + wtot[7];
        nk = tot < KEEPMAX ? tot : KEEPMAX;
    }
    __syncthreads();

    // ---- warp-parallel exact fp32 dots (warp w handles candidates w, w+8, ...) ----
    int n = nk;
    for (int s = w; s < n; s += 8) {
        const float* b = Bmat + (size_t)jl[s] * DD;
        float p = 0.f;
#pragma unroll
        for (int k = 0; k < 32; k++) p += a[lane + 32 * k] * b[lane + 32 * k];
#pragma unroll
        for (int o = 16; o; o >>= 1) p += __shfl_xor_sync(0xffffffffu, p, o);
        if (lane == 0) xs[s] = p;
    }
    __syncthreads();
    if (t == 0) {
        float Sapp = gS[row];
        float Mn = gmax;
        for (int s = 0; s < n; s++) Mn = fmaxf(Mn, xs[s]);
        float S = Sapp * __expf(gmax - Mn);
        for (int s = 0; s < n; s++)
            S += __expf(xs[s] - Mn) - __expf(xap[s] - Mn);
        float inv = 1.0f / S;
        for (int s = 0; s < n; s++) wl[s] = __expf(xs[s] - Mn) * inv;
    }
    __syncthreads();

    float a0 = 0.f, a1 = 0.f, a2 = 0.f, a3 = 0.f;
    for (int s = 0; s < n; s++) {
        int j = jl[s];
        float wv = wl[s];
        float4 vv = *reinterpret_cast<const float4*>(Bmat + (size_t)j * DD + t * 4);
        a0 += wv * vv.x; a1 += wv * vv.y; a2 += wv * vv.z; a3 += wv * vv.w;
    }
    __half2* d = reinterpret_cast<__half2*>(att + (size_t)row * DD + t * 4);
    d[0] = __floats2half2_rn(a0, a1);
    d[1] = __floats2half2_rn(a2, a3);
}

// ======================= column sums of fp16 att -> sumv (both sides, y=2) ===========
__global__ void colsum_kernel(const __half* __restrict__ att1, float* __restrict__ sumv1,
                              const __half* __restrict__ att2, float* __restrict__ sumv2)
{
    const __half* att = blockIdx.y ? att2 : att1;
    float* sumv = blockIdx.y ? sumv2 : sumv1;
    int lane = threadIdx.x & 31, w = threadIdx.x >> 5;
    int col = blockIdx.x * 32 + lane;
    float s = 0.f;
#pragma unroll 8
    for (int r = 0; r < 1024; r++)
        s += __half2float(att[(size_t)(w * 1024 + r) * DD + col]);
    __shared__ float sh[8][33];
    sh[w][lane] = s;
    __syncthreads();
    if (threadIdx.x < 32) {
        float t = 0.f;
#pragma unroll
        for (int q = 0; q < 8; q++) t += sh[q][threadIdx.x];
        sumv[blockIdx.x * 32 + threadIdx.x] = t;
    }
}

// ======================= combined prep casts =======================
#define M1N (N1V * DD)
#define M2N (N2V * DD)
#define WN  (FPAD * DD)
__global__ void prep_kernel(const float* __restrict__ m1, const float* __restrict__ m2,
                            const float* __restrict__ W1, const float* __restrict__ W2,
                            uint8_t* __restrict__ m1q, uint8_t* __restrict__ m2q,
                            __half* __restrict__ w1h, __half* __restrict__ w2h)
{
    int i = blockIdx.x * 256 + threadIdx.x;
    if (i < M1N) {
        __nv_fp8_e4m3 v(m1[i]);
        m1q[i] = *reinterpret_cast<uint8_t*>(&v);
    } else if (i < M1N + M2N) {
        int k = i - M1N;
        __nv_fp8_e4m3 v(m2[k]);
        m2q[k] = *reinterpret_cast<uint8_t*>(&v);
    } else if (i < M1N + M2N + WN) {
        int k = i - M1N - M2N;
        int r = k / DD;
        w1h[k] = __float2half_rn(r < FF ? W1[k] : 0.f);
    } else if (i < M1N + M2N + 2 * WN) {
        int k = i - M1N - M2N - WN;
        int r = k / DD;
        w2h[k] = __float2half_rn(r < FF ? W2[k] : 0.f);
    }
}

// ======================= finalize =======================
__global__ void finalize_kernel(const float* __restrict__ Wf1, const float* __restrict__ bf1,
                                const float* __restrict__ Wf2, const float* __restrict__ bf2,
                                float* __restrict__ out)
{
    int g = blockIdx.x * 8 + (threadIdx.x >> 5);
    int lane = threadIdx.x & 31;
    const float inv = 1.0f / 8192.0f;
    if (g < FF) {
        const float* w = Wf1 + (size_t)g * DD;
        float d = 0.f;
        for (int l = lane; l < DD; l += 32) d += w[l] * g_sumv2[l];
#pragma unroll
        for (int o = 16; o; o >>= 1) d += __shfl_xor_sync(0xffffffffu, d, o);
        if (lane == 0) {
            float filt = 1.0f / (1.0f + __expf(-(d * inv + bf1[g])));
            float t = 0.f;
#pragma unroll
            for (int b = 0; b < 32; b++) t += g_tpart1[g * 32 + b];
            out[g] = t * inv * filt;
        }
    } else if (g < 2 * FF) {
        int f = g - FF;
        const float* w = Wf2 + (size_t)f * DD;
        float d = 0.f;
        for (int l = lane; l < DD; l += 32) d += w[l] * g_sumv1[l];
#pragma unroll
        for (int o = 16; o; o >>= 1) d += __shfl_xor_sync(0xffffffffu, d, o);
        if (lane == 0) {
            float filt = 1.0f / (1.0f + __expf(-(d * inv + bf2[f])));
            float t = 0.f;
#pragma unroll
            for (int b = 0; b < 32; b++) t += g_tpart2[f * 32 + b];
            out[FF + f] = t * inv * filt;
        }
    }
}

// ======================= launch =======================
extern "C" void kernel_launch(void* const* d_in, const int* in_sizes, int n_in,
                              void* d_out, int out_size)
{
    const float* m1  = (const float*)d_in[0];
    const float* m2  = (const float*)d_in[1];
    const float* Wf1 = (const float*)d_in[2];
    const float* bf1 = (const float*)d_in[3];
    const float* Wf2 = (const float*)d_in[4];
    const float* bf2 = (const float*)d_in[5];
    const float* W1  = (const float*)d_in[6];
    const float* b1  = (const float*)d_in[7];
    const float* W2  = (const float*)d_in[8];
    const float* b2  = (const float*)d_in[9];
    float* out = (float*)d_out;

    float *tpart1, *tpart2, *rpm, *rps, *cpm, *cps, *sumv1, *sumv2;
    float *rmaxp, *rsump, *cmaxp, *csump;
    uint8_t *m1q, *m2q, *cmask;
    uint16_t *rmask;
    __half *rawh, *att1h, *att2h, *w1h, *w2h;
    cudaGetSymbolAddress((void**)&rawh,  g_rawh);
    cudaGetSymbolAddress((void**)&m1q,   g_m1q);
    cudaGetSymbolAddress((void**)&m2q,   g_m2q);
    cudaGetSymbolAddress((void**)&att1h, g_att1h);
    cudaGetSymbolAddress((void**)&att2h, g_att2h);
    cudaGetSymbolAddress((void**)&w1h,   g_w1h);
    cudaGetSymbolAddress((void**)&w2h,   g_w2h);
    cudaGetSymbolAddress((void**)&tpart1, g_tpart1);
    cudaGetSymbolAddress((void**)&tpart2, g_tpart2);
    cudaGetSymbolAddress((void**)&rpm, g_rpm);
    cudaGetSymbolAddress((void**)&rps, g_rps);
    cudaGetSymbolAddress((void**)&cpm, g_cpm);
    cudaGetSymbolAddress((void**)&cps, g_cps);
    cudaGetSymbolAddress((void**)&rmask, g_rmask);
    cudaGetSymbolAddress((void**)&cmask, g_cmask);
    cudaGetSymbolAddress((void**)&sumv1, g_sumv1);
    cudaGetSymbolAddress((void**)&sumv2, g_sumv2);
    cudaGetSymbolAddress((void**)&rmaxp, g_rmax);
    cudaGetSymbolAddress((void**)&rsump, g_rsum);
    cudaGetSymbolAddress((void**)&cmaxp, g_cmax);
    cudaGetSymbolAddress((void**)&csump, g_csum);

    cudaFuncSetAttribute(hgemm8, cudaFuncAttributeMaxDynamicSharedMemorySize, 92160);
    cudaFuncSetAttribute(tgemm,  cudaFuncAttributeMaxDynamicSharedMemorySize, 92160);

    // 0) combined prep casts
    prep_kernel<<<(M1N + M2N + 2 * WN + 255) / 256, 256>>>(
        m1, m2, W1, W2, m1q, m2q, w1h, w2h);

    // 1) approx raw = m1 @ m2^T (e4m3 MMA): fp16 store + fused stats + candidate bitmasks
    hgemm8<<<dim3(N2V / 256, N1V / 128), 256, 92160>>>(
        m1q, m2q, rawh, N2V, DD, DD / 64, rpm, rps, cpm, cps, rmask, cmask);

    // 2) merge approx stats (M, S)
    stats_merge_kernel<<<(N1V + N2V) / 8, 256>>>();

    // 3) refine + gather (mask scan -> exact fp32 logits -> exact softmax -> fp16 att)
    refine_gather_kernel<0><<<N1V, 256>>>(m1, m2, rmask, rawh, rmaxp, rsump, att2h);
    refine_gather_kernel<1><<<N2V, 256>>>(m2, m1, cmask, rawh, cmaxp, csump, att1h);

    // 4) column sums for the filter path (both sides, one launch)
    colsum_kernel<<<dim3(DD / 32, 2), 256>>>(att1h, sumv1, att2h, sumv2);

    // 5) transform GEMMs merged (z selects W1/att1 vs W2/att2), fused tanh+rowsum
    tgemm<<<dim3(N2V / 256, FPAD / 128, 2), 256, 92160>>>(
        w1h, att1h, w2h, att2h, DD, DD / 32, FF, b1, tpart1, b2, tpart2);

    // 6) filters + outputs
    finalize_kernel<<<200, 256>>>(Wf1, bf1, Wf2, bf2, out);
}